// round 11
// baseline (speedup 1.0000x reference)
#include <cuda_runtime.h>
#include <math.h>

#define T_  256
#define B_  128
#define NN  17
#define DD  2176   // 17*128
#define GG  1024   // 4*256
#define LH_ 256
#define NC_ 625

__constant__ int c_conn[19][2] = {
  {15,13},{13,11},{16,14},{14,12},{11,12},{5,11},{6,12},{5,6},{5,7},{6,8},
  {7,9},{8,10},{1,2},{0,1},{0,2},{1,3},{2,4},{3,5},{4,6}
};

// ---- scratch (device globals: the sanctioned no-alloc scratch) ----
__device__ float g_AHAT[NN*NN];
__device__ float g_AmI[NN*NN];
__device__ float g_S[(size_t)T_*B_*NN*128];      // 285 MB: 0.5*(relu1_p1 [+agg b=0] + relu1_p2)
__device__ float g_H10[(size_t)T_*NN*128];       // relu1 of pose1, b=0 (post-agg)
__device__ float g_E[(size_t)T_*NN*128];         // 0.5*(A-I)@H10
__device__ float g_V[(size_t)DD*GG];             // folded W2 @ Wih_f^T (per node)
__device__ float g_WihT[(size_t)DD*GG];
__device__ float g_WihTb[(size_t)DD*GG];
__device__ float g_WhhT[(size_t)LH_*GG];
__device__ float g_biasV[GG];
__device__ float g_pre[(size_t)T_*B_*GG];        // 134 MB forward LSTM pre-activations
__device__ float g_corr[(size_t)T_*GG];
__device__ float g_F[(size_t)B_*DD];             // feats at t=T-1 (for backward step)
__device__ float g_preb[(size_t)B_*GG];
__device__ float g_hA[B_*LH_];
__device__ float g_hB[B_*LH_];
__device__ float g_cst[B_*LH_];
__device__ float g_hbk[B_*LH_];
__device__ float g_pool[B_*512];

// ---- build normalized adjacency (matches PyG GCNConv norm, f64 like ref) ----
__global__ void k_init_ahat() {
  if (threadIdx.x != 0 || blockIdx.x != 0) return;
  double deg[NN];
  for (int i = 0; i < NN; i++) deg[i] = 1.0;              // self loops
  for (int e = 0; e < 19; e++) deg[c_conn[e][1]] += 1.0;  // in-degree on dst
  double dis[NN];
  for (int i = 0; i < NN; i++) dis[i] = 1.0 / sqrt(deg[i]);
  double A[NN][NN];
  for (int i = 0; i < NN; i++) for (int j = 0; j < NN; j++) A[i][j] = 0.0;
  for (int e = 0; e < 19; e++) {
    int s = c_conn[e][0], d = c_conn[e][1];
    A[d][s] += dis[s] * dis[d];
  }
  for (int i = 0; i < NN; i++) A[i][i] += dis[i] * dis[i];
  for (int i = 0; i < NN; i++) for (int j = 0; j < NN; j++) {
    float v = (float)A[i][j];
    g_AHAT[i*NN+j] = v;
    g_AmI[i*NN+j]  = v - (i == j ? 1.f : 0.f);
  }
}

__global__ void k_transpose(const float* __restrict__ in, float* __restrict__ out, int R, int C) {
  int idx = blockIdx.x * 256 + threadIdx.x;
  if (idx < R * C) {
    int r = idx / C, c = idx - r * C;
    out[(size_t)c * R + r] = in[idx];
  }
}

// biasV[n] = bih_f[n]+bhh_f[n] + sum_{i,c} b2[c]*Wih_f[n, i*128+c]   (b2 folded through Wih)
__global__ void k_biasV(const float* __restrict__ Wih, const float* __restrict__ bih,
                        const float* __restrict__ bhh, const float* __restrict__ b2) {
  int n = blockIdx.x * 256 + threadIdx.x;
  if (n >= GG) return;
  float acc = bih[n] + bhh[n];
  const float* row = Wih + (size_t)n * DD;
  for (int ic = 0; ic < DD; ic++) acc += b2[ic & 127] * row[ic];
  g_biasV[n] = acc;
}

// ---- generic SGEMM: C = A(MxK,rm) * B(KxN,rm) [+bias[n]], 128x128 tile, 8x8/thread ----
__global__ void __launch_bounds__(256, 2)
k_sgemm(int M, int N, int K,
        const float* __restrict__ A, const float* __restrict__ B,
        float* __restrict__ C, const float* __restrict__ bias,
        long long sA, long long sB, long long sC) {
  A += (size_t)blockIdx.z * (size_t)sA;
  B += (size_t)blockIdx.z * (size_t)sB;
  C += (size_t)blockIdx.z * (size_t)sC;
  __shared__ float As[8][128];
  __shared__ float Bs[8][128];
  int tid = threadIdx.x;
  int m0 = blockIdx.y * 128, n0 = blockIdx.x * 128;
  int tx = tid & 15, ty = tid >> 4;
  int arow = tid >> 1, ak = (tid & 1) << 2;
  int bk = tid >> 5, bn = (tid & 31) << 2;
  float acc[8][8];
#pragma unroll
  for (int i = 0; i < 8; i++)
#pragma unroll
    for (int j = 0; j < 8; j++) acc[i][j] = 0.f;

  for (int k0 = 0; k0 < K; k0 += 8) {
    float4 av = make_float4(0.f, 0.f, 0.f, 0.f);
    if (m0 + arow < M) av = *(const float4*)(A + (size_t)(m0 + arow) * K + k0 + ak);
    float4 bv = make_float4(0.f, 0.f, 0.f, 0.f);
    if (n0 + bn < N) bv = *(const float4*)(B + (size_t)(k0 + bk) * N + n0 + bn);
    __syncthreads();
    As[ak+0][arow] = av.x; As[ak+1][arow] = av.y;
    As[ak+2][arow] = av.z; As[ak+3][arow] = av.w;
    *(float4*)&Bs[bk][bn] = bv;
    __syncthreads();
#pragma unroll
    for (int kk = 0; kk < 8; kk++) {
      float a[8], b[8];
      *(float4*)&a[0] = *(const float4*)&As[kk][ty*8];
      *(float4*)&a[4] = *(const float4*)&As[kk][ty*8+4];
      *(float4*)&b[0] = *(const float4*)&Bs[kk][tx*8];
      *(float4*)&b[4] = *(const float4*)&Bs[kk][tx*8+4];
#pragma unroll
      for (int i = 0; i < 8; i++)
#pragma unroll
        for (int j = 0; j < 8; j++) acc[i][j] += a[i] * b[j];
    }
  }
#pragma unroll
  for (int i = 0; i < 8; i++) {
    int m = m0 + ty*8 + i;
    if (m >= M) continue;
    float* cp = C + (size_t)m * N + n0 + tx*8;
#pragma unroll
    for (int j = 0; j < 8; j++) {
      float v = acc[i][j];
      if (bias) v += bias[n0 + tx*8 + j];
      cp[j] = v;
    }
  }
}

// ---- GCN layer 1 (fused both poses, relu, agg for b=0, 0.5*sum) ----
__global__ void k_layer1(const float* __restrict__ pose1, const float* __restrict__ pose2,
                         const float* __restrict__ W1, const float* __restrict__ b1) {
  int bid = blockIdx.x;          // t*128 + b
  int c = threadIdx.x;           // 0..127
  int b = bid & 127, t = bid >> 7;
  __shared__ float sp1[NN*3], sp2[NN*3];
  __shared__ float sg[NN*128];
  size_t pbase = ((size_t)b * T_ + t) * NN * 3;
  if (c < NN*3) { sp1[c] = pose1[pbase + c]; sp2[c] = pose2[pbase + c]; }
  __syncthreads();
  float w0 = W1[c], w1 = W1[128 + c], w2 = W1[256 + c];
  float bb = b1[c];
  size_t srow = ((size_t)t * B_ + b) * NN;
  if (b == 0) {
    for (int i = 0; i < NN; i++)
      sg[i*128 + c] = sp1[i*3]*w0 + sp1[i*3+1]*w1 + sp1[i*3+2]*w2;
    __syncthreads();
    for (int i = 0; i < NN; i++) {
      float agg = 0.f;
      for (int j = 0; j < NN; j++) agg += g_AHAT[i*NN+j] * sg[j*128 + c];
      float v1 = fmaxf(agg + bb, 0.f);
      float v2 = fmaxf(sp2[i*3]*w0 + sp2[i*3+1]*w1 + sp2[i*3+2]*w2 + bb, 0.f);
      g_H10[((size_t)t*NN + i)*128 + c] = v1;
      g_S[(srow + i)*128 + c] = 0.5f * (v1 + v2);
    }
  } else {
    for (int i = 0; i < NN; i++) {
      float v1 = fmaxf(sp1[i*3]*w0 + sp1[i*3+1]*w1 + sp1[i*3+2]*w2 + bb, 0.f);
      float v2 = fmaxf(sp2[i*3]*w0 + sp2[i*3+1]*w1 + sp2[i*3+2]*w2 + bb, 0.f);
      g_S[(srow + i)*128 + c] = 0.5f * (v1 + v2);
    }
  }
}

// E[t] = 0.5*(A-I) @ H10[t]
__global__ void k_E() {
  int t = blockIdx.x, c = threadIdx.x;
  __shared__ float sh[NN*128];
  for (int i = 0; i < NN; i++) sh[i*128 + c] = g_H10[((size_t)t*NN + i)*128 + c];
  __syncthreads();
  for (int i = 0; i < NN; i++) {
    float acc = 0.f;
    for (int j = 0; j < NN; j++) acc += g_AmI[i*NN+j] * sh[j*128 + c];
    g_E[((size_t)t*NN + i)*128 + c] = 0.5f * acc;
  }
}

// pre[t, b=0, :] += corr[t, :]
__global__ void k_addcorr() {
  int idx = blockIdx.x * 256 + threadIdx.x;   // 256*1024
  int t = idx >> 10, n = idx & 1023;
  g_pre[(size_t)t * B_ * GG + n] += g_corr[idx];
}

// F[b=0] += E[T-1] @ W2   (layer-2 agg correction for the backward-step features)
__global__ void k_fixF0(const float* __restrict__ W2) {
  int i = blockIdx.x, cc = threadIdx.x;
  __shared__ float se[128];
  se[cc] = g_E[((size_t)(T_-1)*NN + i)*128 + cc];
  __syncthreads();
  float acc = 0.f;
  for (int k = 0; k < 128; k++) acc += se[k] * W2[k*128 + cc];
  g_F[i*128 + cc] += acc;
}

__device__ __forceinline__ float sigf(float x) { return 1.f / (1.f + expf(-x)); }

// one forward LSTM step: z = pre_t + h_in @ Whh^T; gates; update c; write h_out
__global__ void __launch_bounds__(256)
k_lstm_step(const float* __restrict__ pre_t, const float* __restrict__ h_in,
            float* __restrict__ h_out, float* __restrict__ c_st,
            const float* __restrict__ WhhT) {
  int b0 = blockIdx.x * 16;
  int j0 = blockIdx.y * 32;
  int tid = threadIdx.x;
  int jl = tid & 31;
  int bq = tid >> 5;                 // 0..7
  __shared__ float hs[16][32];
  __shared__ float ws[32][128];      // [kk][g*32 + jl]
  float acc[2][4];
#pragma unroll
  for (int a = 0; a < 2; a++)
#pragma unroll
    for (int g = 0; g < 4; g++) acc[a][g] = 0.f;

  for (int k0 = 0; k0 < LH_; k0 += 32) {
#pragma unroll
    for (int r = 0; r < 2; r++) {
      int idx = tid + r * 256;
      int bl = idx >> 5, kk = idx & 31;
      hs[bl][kk] = h_in[(b0 + bl) * LH_ + k0 + kk];
    }
#pragma unroll
    for (int r = 0; r < 16; r++) {
      int idx = tid + r * 256;
      int kk = idx >> 7, col = idx & 127;
      int g = col >> 5, jj = col & 31;
      ws[kk][col] = WhhT[(size_t)(k0 + kk) * GG + g * 256 + j0 + jj];
    }
    __syncthreads();
#pragma unroll
    for (int kk = 0; kk < 32; kk++) {
      float a0 = hs[bq][kk], a1 = hs[bq + 8][kk];
#pragma unroll
      for (int g = 0; g < 4; g++) {
        float w = ws[kk][g*32 + jl];
        acc[0][g] += a0 * w;
        acc[1][g] += a1 * w;
      }
    }
    __syncthreads();
  }
#pragma unroll
  for (int a = 0; a < 2; a++) {
    int b = b0 + bq + a * 8;
    int j = j0 + jl;
    const float* pr = pre_t + (size_t)b * GG;
    float zi = acc[a][0] + pr[j];
    float zf = acc[a][1] + pr[256 + j];
    float zg = acc[a][2] + pr[512 + j];
    float zo = acc[a][3] + pr[768 + j];
    float co = c_st[b * LH_ + j];
    float cn = sigf(zf) * co + sigf(zi) * tanhf(zg);
    c_st[b * LH_ + j] = cn;
    h_out[b * LH_ + j] = sigf(zo) * tanhf(cn);
  }
}

// backward direction = single step from zero state on pre_b
__global__ void k_backstep(const float* __restrict__ bih, const float* __restrict__ bhh) {
  int b = blockIdx.x, j = threadIdx.x;
  const float* pr = g_preb + (size_t)b * GG;
  float zi = pr[j]       + bih[j]       + bhh[j];
  float zg = pr[512 + j] + bih[512 + j] + bhh[512 + j];
  float zo = pr[768 + j] + bih[768 + j] + bhh[768 + j];
  float cn = sigf(zi) * tanhf(zg);
  g_hbk[b * LH_ + j] = sigf(zo) * tanhf(cn);
}

__global__ void k_pool(const float* __restrict__ hf, float* outp) {
  int idx = blockIdx.x * 256 + threadIdx.x;   // 128*512
  int b = idx >> 9, d = idx & 511;
  float v = (d < 256) ? hf[b * 256 + d] : g_hbk[b * 256 + d - 256];
  v = fmaxf(v, 0.f);
  g_pool[idx] = v;
  if (outp) outp[idx] = v;
}

__global__ void k_cls(const float* __restrict__ Wc, const float* __restrict__ bc,
                      float* __restrict__ outc) {
  int b = blockIdx.x;
  int m = blockIdx.y * 128 + threadIdx.x;
  __shared__ float sp[512];
  int t = threadIdx.x;
  sp[t] = g_pool[b*512 + t]; sp[t+128] = g_pool[b*512 + t + 128];
  sp[t+256] = g_pool[b*512 + t + 256]; sp[t+384] = g_pool[b*512 + t + 384];
  __syncthreads();
  if (m < NC_) {
    float acc = bc[m];
    const float* wr = Wc + (size_t)m * 512;
    for (int d = 0; d < 512; d++) acc += sp[d] * wr[d];
    outc[(size_t)b * NC_ + m] = acc;
  }
}

extern "C" void kernel_launch(void* const* d_in, const int* in_sizes, int n_in,
                              void* d_out, int out_size) {
  const float* pose1 = (const float*)d_in[0];
  const float* pose2 = (const float*)d_in[1];
  const float* W1    = (const float*)d_in[2];
  const float* b1    = (const float*)d_in[3];
  const float* W2    = (const float*)d_in[4];
  const float* b2    = (const float*)d_in[5];
  const float* Wih_f = (const float*)d_in[6];
  const float* Whh_f = (const float*)d_in[7];
  const float* bih_f = (const float*)d_in[8];
  const float* bhh_f = (const float*)d_in[9];
  const float* Wih_b = (const float*)d_in[10];
  const float* Whh_b = (const float*)d_in[11];
  const float* bih_b = (const float*)d_in[12];
  const float* bhh_b = (const float*)d_in[13];
  const float* Wc    = (const float*)d_in[14];
  const float* bc    = (const float*)d_in[15];
  (void)Whh_b; (void)in_sizes; (void)n_in;
  float* out = (float*)d_out;

  void *pWihT, *pWihTb, *pWhhT, *pV, *pS, *pPre, *pE, *pCorr, *pF, *pPreb, *pBias, *pHA, *pHB, *pC;
  cudaGetSymbolAddress(&pWihT,  g_WihT);
  cudaGetSymbolAddress(&pWihTb, g_WihTb);
  cudaGetSymbolAddress(&pWhhT,  g_WhhT);
  cudaGetSymbolAddress(&pV,     g_V);
  cudaGetSymbolAddress(&pS,     g_S);
  cudaGetSymbolAddress(&pPre,   g_pre);
  cudaGetSymbolAddress(&pE,     g_E);
  cudaGetSymbolAddress(&pCorr,  g_corr);
  cudaGetSymbolAddress(&pF,     g_F);
  cudaGetSymbolAddress(&pPreb,  g_preb);
  cudaGetSymbolAddress(&pBias,  g_biasV);
  cudaGetSymbolAddress(&pHA,    g_hA);
  cudaGetSymbolAddress(&pHB,    g_hB);
  cudaGetSymbolAddress(&pC,     g_cst);

  // output layout (pool first, then cls); adapt to what the harness allocated
  float* pool_dst = nullptr;
  float* cls_dst  = nullptr;
  if (out_size == B_*512 + B_*NC_)      { pool_dst = out; cls_dst = out + B_*512; }
  else if (out_size == B_*NC_)          { cls_dst = out; }
  else if (out_size == B_*512)          { pool_dst = out; }
  else { pool_dst = out; if (out_size >= B_*512 + B_*NC_) cls_dst = out + B_*512; }

  k_init_ahat<<<1, 32>>>();
  k_transpose<<<(GG*DD + 255)/256, 256>>>(Wih_f, (float*)pWihT, GG, DD);
  k_transpose<<<(GG*DD + 255)/256, 256>>>(Wih_b, (float*)pWihTb, GG, DD);
  k_transpose<<<(GG*LH_ + 255)/256, 256>>>(Whh_f, (float*)pWhhT, GG, LH_);
  k_biasV<<<4, 256>>>(Wih_f, bih_f, bhh_f, b2);

  // V_i = W2 @ WihT_f[i]  -> folded layer-2 weight (17 batched 128x1024 GEMMs)
  k_sgemm<<<dim3(8, 1, 17), 256>>>(128, GG, 128, W2, (const float*)pWihT, (float*)pV,
                                   nullptr, 0LL, (long long)128*GG, (long long)128*GG);

  // GCN layer 1 fused -> S (and H10 for b=0), then E = 0.5*(A-I)@H10
  k_layer1<<<T_*B_, 128>>>(pose1, pose2, W1, b1);
  k_E<<<T_, 128>>>();

  // pre_f = S @ V + biasV   (the 146 GFLOP GEMM)
  k_sgemm<<<dim3(GG/128, (T_*B_)/128, 1), 256>>>(T_*B_, GG, DD, (const float*)pS,
                                                 (const float*)pV, (float*)pPre,
                                                 (const float*)pBias, 0LL, 0LL, 0LL);
  // b=0 correction: corr = E @ V ; pre[t,0,:] += corr[t]
  k_sgemm<<<dim3(GG/128, T_/128, 1), 256>>>(T_, GG, DD, (const float*)pE,
                                            (const float*)pV, (float*)pCorr,
                                            nullptr, 0LL, 0LL, 0LL);
  k_addcorr<<<(T_*GG)/256, 256>>>();

  // backward features at t=T-1: F = S[T-1] @ W2 + b2 (rows (b,i)); fix b=0 with E
  const float* Slast = (const float*)pS + (size_t)(T_-1) * B_ * NN * 128;
  k_sgemm<<<dim3(1, (B_*NN)/128, 1), 256>>>(B_*NN, 128, 128, Slast, W2, (float*)pF,
                                            b2, 0LL, 0LL, 0LL);
  k_fixF0<<<NN, 128>>>(W2);
  // pre_b = F @ Wih_b^T  (biases added in k_backstep)
  k_sgemm<<<dim3(GG/128, 1, 1), 256>>>(B_, GG, DD, (const float*)pF,
                                       (const float*)pWihTb, (float*)pPreb,
                                       nullptr, 0LL, 0LL, 0LL);

  // forward recurrence: 256 sequential steps, ping-pong h buffers
  cudaMemsetAsync(pHA, 0, (size_t)B_ * LH_ * sizeof(float));
  cudaMemsetAsync(pC,  0, (size_t)B_ * LH_ * sizeof(float));
  float* hin = (float*)pHA;
  float* hout = (float*)pHB;
  for (int t = 0; t < T_; t++) {
    k_lstm_step<<<dim3(B_/16, LH_/32), 256>>>((const float*)pPre + (size_t)t * B_ * GG,
                                              hin, hout, (float*)pC, (const float*)pWhhT);
    float* tmp = hin; hin = hout; hout = tmp;
  }
  // final forward h is in `hin`

  k_backstep<<<B_, 256>>>(bih_b, bhh_b);
  k_pool<<<(B_*512)/256, 256>>>(hin, pool_dst);
  if (cls_dst) k_cls<<<dim3(B_, 5), 128>>>(Wc, bc, cls_dst);
}

// round 13
// speedup vs baseline: 1.6029x; 1.6029x over previous
#include <cuda_runtime.h>
#include <cuda_bf16.h>
#include <math.h>
#include <stdint.h>

#define T_  256
#define B_  128
#define NN  17
#define DD  2176   // 17*128
#define GG  1024   // 4*256
#define LH_ 256
#define NC_ 625

__constant__ int c_conn[19][2] = {
  {15,13},{13,11},{16,14},{14,12},{11,12},{5,11},{6,12},{5,6},{5,7},{6,8},
  {7,9},{8,10},{1,2},{0,1},{0,2},{1,3},{2,4},{3,5},{4,6}
};

// ---- scratch (device globals) ----
__device__ float g_AHAT[NN*NN];
__device__ float g_AmI[NN*NN];
__device__ __nv_bfloat16 g_Shi[(size_t)T_*B_*DD];
__device__ __nv_bfloat16 g_Slo[(size_t)T_*B_*DD];
__device__ float g_Slast[(size_t)B_*DD];
__device__ float g_H10[(size_t)T_*NN*128];
__device__ float g_E[(size_t)T_*DD];
__device__ __nv_bfloat16 g_Ehi[(size_t)T_*DD];
__device__ __nv_bfloat16 g_Elo[(size_t)T_*DD];
__device__ float g_V[(size_t)DD*GG];
__device__ __nv_bfloat16 g_VtHi[(size_t)GG*DD];
__device__ __nv_bfloat16 g_VtLo[(size_t)GG*DD];
__device__ __nv_bfloat16 g_WbHi[(size_t)GG*DD];
__device__ __nv_bfloat16 g_WbLo[(size_t)GG*DD];
__device__ float g_WihT[(size_t)DD*GG];
__device__ float g_WhhT[(size_t)LH_*GG];
__device__ float g_biasV[GG];
__device__ float g_pre[(size_t)T_*B_*GG];
__device__ float g_corr[(size_t)T_*GG];
__device__ float g_F[(size_t)B_*DD];
__device__ __nv_bfloat16 g_Fhi[(size_t)B_*DD];
__device__ __nv_bfloat16 g_Flo[(size_t)B_*DD];
__device__ float g_preb[(size_t)B_*GG];
__device__ float g_hA[B_*LH_];
__device__ float g_hB[B_*LH_];
__device__ float g_cst[B_*LH_];
__device__ float g_hbk[B_*LH_];
__device__ float g_pool[B_*512];

// ============================ helpers ============================
__device__ __forceinline__ uint32_t smem_u32(const void* p) {
  uint32_t a;
  asm("{ .reg .u64 t; cvta.to.shared.u64 t, %1; cvt.u32.u64 %0, t; }" : "=r"(a) : "l"(p));
  return a;
}
__device__ __forceinline__ void cp16(uint32_t saddr, const void* g) {
  asm volatile("cp.async.cg.shared.global [%0], [%1], 16;" :: "r"(saddr), "l"(g));
}
__device__ __forceinline__ void ldsm4(uint32_t addr, uint32_t& r0, uint32_t& r1,
                                      uint32_t& r2, uint32_t& r3) {
  asm volatile("ldmatrix.sync.aligned.m8n8.x4.shared.b16 {%0,%1,%2,%3}, [%4];"
               : "=r"(r0), "=r"(r1), "=r"(r2), "=r"(r3) : "r"(addr));
}
__device__ __forceinline__ void mma16816(float* c, const uint32_t* a, uint32_t b0, uint32_t b1) {
  asm volatile(
    "mma.sync.aligned.m16n8k16.row.col.f32.bf16.bf16.f32 "
    "{%0,%1,%2,%3}, {%4,%5,%6,%7}, {%8,%9}, {%0,%1,%2,%3};"
    : "+f"(c[0]), "+f"(c[1]), "+f"(c[2]), "+f"(c[3])
    : "r"(a[0]), "r"(a[1]), "r"(a[2]), "r"(a[3]), "r"(b0), "r"(b1));
}

// ============================ setup kernels ============================
__global__ void k_init_ahat() {
  if (threadIdx.x != 0 || blockIdx.x != 0) return;
  double deg[NN];
  for (int i = 0; i < NN; i++) deg[i] = 1.0;
  for (int e = 0; e < 19; e++) deg[c_conn[e][1]] += 1.0;
  double dis[NN];
  for (int i = 0; i < NN; i++) dis[i] = 1.0 / sqrt(deg[i]);
  double A[NN][NN];
  for (int i = 0; i < NN; i++) for (int j = 0; j < NN; j++) A[i][j] = 0.0;
  for (int e = 0; e < 19; e++) {
    int s = c_conn[e][0], d = c_conn[e][1];
    A[d][s] += dis[s] * dis[d];
  }
  for (int i = 0; i < NN; i++) A[i][i] += dis[i] * dis[i];
  for (int i = 0; i < NN; i++) for (int j = 0; j < NN; j++) {
    float v = (float)A[i][j];
    g_AHAT[i*NN+j] = v;
    g_AmI[i*NN+j]  = v - (i == j ? 1.f : 0.f);
  }
}

__global__ void k_transpose(const float* __restrict__ in, float* __restrict__ out, int R, int C) {
  int idx = blockIdx.x * 256 + threadIdx.x;
  if (idx < R * C) {
    int r = idx / C, c = idx - r * C;
    out[(size_t)c * R + r] = in[idx];
  }
}

__global__ void k_split(const float* __restrict__ in, __nv_bfloat16* __restrict__ hi,
                        __nv_bfloat16* __restrict__ lo, int n4) {
  int i = blockIdx.x * 256 + threadIdx.x;
  if (i >= n4) return;
  float4 v = ((const float4*)in)[i];
  __nv_bfloat16 hx = __float2bfloat16(v.x), hy = __float2bfloat16(v.y);
  __nv_bfloat16 hz = __float2bfloat16(v.z), hw = __float2bfloat16(v.w);
  __nv_bfloat16 lx = __float2bfloat16(v.x - __bfloat162float(hx));
  __nv_bfloat16 ly = __float2bfloat16(v.y - __bfloat162float(hy));
  __nv_bfloat16 lz = __float2bfloat16(v.z - __bfloat162float(hz));
  __nv_bfloat16 lw = __float2bfloat16(v.w - __bfloat162float(hw));
  __nv_bfloat162* H = (__nv_bfloat162*)hi;
  __nv_bfloat162* L = (__nv_bfloat162*)lo;
  H[2*i]   = __halves2bfloat162(hx, hy);
  H[2*i+1] = __halves2bfloat162(hz, hw);
  L[2*i]   = __halves2bfloat162(lx, ly);
  L[2*i+1] = __halves2bfloat162(lz, lw);
}

// transpose+split: in [DD][GG] fp32 -> out [GG][DD] bf16 hi/lo
__global__ void k_tsplit(const float* __restrict__ in, __nv_bfloat16* __restrict__ hi,
                         __nv_bfloat16* __restrict__ lo) {
  __shared__ float t[32][33];
  int bx = blockIdx.x;
  int by = blockIdx.y;
  int tx = threadIdx.x & 31, ty = threadIdx.x >> 5;
#pragma unroll
  for (int j = 0; j < 4; j++)
    t[ty + j*8][tx] = in[(size_t)(by*32 + ty + j*8) * GG + bx*32 + tx];
  __syncthreads();
#pragma unroll
  for (int j = 0; j < 4; j++) {
    float v = t[tx][ty + j*8];
    size_t o = (size_t)(bx*32 + ty + j*8) * DD + by*32 + tx;
    __nv_bfloat16 h = __float2bfloat16(v);
    hi[o] = h;
    lo[o] = __float2bfloat16(v - __bfloat162float(h));
  }
}

__global__ void k_biasV(const float* __restrict__ Wih, const float* __restrict__ bih,
                        const float* __restrict__ bhh, const float* __restrict__ b2) {
  int n = blockIdx.x;
  float acc = 0.f;
  const float* row = Wih + (size_t)n * DD;
  for (int ic = threadIdx.x; ic < DD; ic += 256) acc += b2[ic & 127] * row[ic];
  __shared__ float r[256];
  r[threadIdx.x] = acc;
  __syncthreads();
  for (int s = 128; s > 0; s >>= 1) {
    if (threadIdx.x < s) r[threadIdx.x] += r[threadIdx.x + s];
    __syncthreads();
  }
  if (threadIdx.x == 0) g_biasV[n] = r[0] + bih[n] + bhh[n];
}

// ---- generic SIMT SGEMM (small folds only) ----
__global__ void __launch_bounds__(256, 2)
k_sgemm(int M, int N, int K,
        const float* __restrict__ A, const float* __restrict__ B,
        float* __restrict__ C, const float* __restrict__ bias,
        long long sA, long long sB, long long sC) {
  A += (size_t)blockIdx.z * (size_t)sA;
  B += (size_t)blockIdx.z * (size_t)sB;
  C += (size_t)blockIdx.z * (size_t)sC;
  __shared__ float As[8][128];
  __shared__ float Bs[8][128];
  int tid = threadIdx.x;
  int m0 = blockIdx.y * 128, n0 = blockIdx.x * 128;
  int tx = tid & 15, ty = tid >> 4;
  int arow = tid >> 1, ak = (tid & 1) << 2;
  int bk = tid >> 5, bn = (tid & 31) << 2;
  float acc[8][8];
#pragma unroll
  for (int i = 0; i < 8; i++)
#pragma unroll
    for (int j = 0; j < 8; j++) acc[i][j] = 0.f;

  for (int k0 = 0; k0 < K; k0 += 8) {
    float4 av = make_float4(0.f, 0.f, 0.f, 0.f);
    if (m0 + arow < M) av = *(const float4*)(A + (size_t)(m0 + arow) * K + k0 + ak);
    float4 bv = make_float4(0.f, 0.f, 0.f, 0.f);
    if (n0 + bn < N) bv = *(const float4*)(B + (size_t)(k0 + bk) * N + n0 + bn);
    __syncthreads();
    As[ak+0][arow] = av.x; As[ak+1][arow] = av.y;
    As[ak+2][arow] = av.z; As[ak+3][arow] = av.w;
    *(float4*)&Bs[bk][bn] = bv;
    __syncthreads();
#pragma unroll
    for (int kk = 0; kk < 8; kk++) {
      float a[8], b[8];
      *(float4*)&a[0] = *(const float4*)&As[kk][ty*8];
      *(float4*)&a[4] = *(const float4*)&As[kk][ty*8+4];
      *(float4*)&b[0] = *(const float4*)&Bs[kk][tx*8];
      *(float4*)&b[4] = *(const float4*)&Bs[kk][tx*8+4];
#pragma unroll
      for (int i = 0; i < 8; i++)
#pragma unroll
        for (int j = 0; j < 8; j++) acc[i][j] += a[i] * b[j];
    }
  }
#pragma unroll
  for (int i = 0; i < 8; i++) {
    int m = m0 + ty*8 + i;
    if (m >= M) continue;
    float* cp = C + (size_t)m * N + n0 + tx*8;
#pragma unroll
    for (int j = 0; j < 8; j++) {
      float v = acc[i][j];
      if (bias) v += bias[n0 + tx*8 + j];
      cp[j] = v;
    }
  }
}

// ---- GCN layer 1 ----
__global__ void k_layer1(const float* __restrict__ pose1, const float* __restrict__ pose2,
                         const float* __restrict__ W1, const float* __restrict__ b1) {
  int bid = blockIdx.x;
  int c = threadIdx.x;
  int b = bid & 127, t = bid >> 7;
  __shared__ float sp1[NN*3], sp2[NN*3];
  __shared__ float sg[NN*128];
  size_t pbase = ((size_t)b * T_ + t) * NN * 3;
  if (c < NN*3) { sp1[c] = pose1[pbase + c]; sp2[c] = pose2[pbase + c]; }
  __syncthreads();
  float w0 = W1[c], w1 = W1[128 + c], w2 = W1[256 + c];
  float bb = b1[c];
  size_t srow = ((size_t)t * B_ + b) * NN;
  for (int i = 0; i < NN; i++) {
    float v1, v2;
    if (b == 0) {
      if (i == 0) {
        for (int ii = 0; ii < NN; ii++)
          sg[ii*128 + c] = sp1[ii*3]*w0 + sp1[ii*3+1]*w1 + sp1[ii*3+2]*w2;
        __syncthreads();
      }
      float agg = 0.f;
      for (int j = 0; j < NN; j++) agg += g_AHAT[i*NN+j] * sg[j*128 + c];
      v1 = fmaxf(agg + bb, 0.f);
      g_H10[((size_t)t*NN + i)*128 + c] = v1;
    } else {
      v1 = fmaxf(sp1[i*3]*w0 + sp1[i*3+1]*w1 + sp1[i*3+2]*w2 + bb, 0.f);
    }
    v2 = fmaxf(sp2[i*3]*w0 + sp2[i*3+1]*w1 + sp2[i*3+2]*w2 + bb, 0.f);
    float s = 0.5f * (v1 + v2);
    size_t o = (srow + i) * 128 + c;
    __nv_bfloat16 h = __float2bfloat16(s);
    g_Shi[o] = h;
    g_Slo[o] = __float2bfloat16(s - __bfloat162float(h));
    if (t == T_-1) g_Slast[((size_t)b*NN + i)*128 + c] = s;
  }
}

__global__ void k_E() {
  int t = blockIdx.x, c = threadIdx.x;
  __shared__ float sh[NN*128];
  for (int i = 0; i < NN; i++) sh[i*128 + c] = g_H10[((size_t)t*NN + i)*128 + c];
  __syncthreads();
  for (int i = 0; i < NN; i++) {
    float acc = 0.f;
    for (int j = 0; j < NN; j++) acc += g_AmI[i*NN+j] * sh[j*128 + c];
    g_E[((size_t)t*NN + i)*128 + c] = 0.5f * acc;
  }
}

__global__ void k_addcorr() {
  int idx = blockIdx.x * 256 + threadIdx.x;
  int t = idx >> 10, n = idx & 1023;
  g_pre[(size_t)t * B_ * GG + n] += g_corr[idx];
}

__global__ void k_fixF0(const float* __restrict__ W2) {
  int i = blockIdx.x, cc = threadIdx.x;
  __shared__ float se[128];
  se[cc] = g_E[((size_t)(T_-1)*NN + i)*128 + cc];
  __syncthreads();
  float acc = 0.f;
  for (int k = 0; k < 128; k++) acc += se[k] * W2[k*128 + cc];
  g_F[i*128 + cc] += acc;
}

// ============================ mma.sync split-bf16 GEMM ============================
// C[M,1024] = (Ahi+Alo)[M,2176] @ (Bhi+Blo)^T ; B stored [1024][2176] (K-major).
// 128x128 CTA tile, 8 warps (32x64 warp tile), K-chunk 64, cp.async double-buffered.
#define KC   64
#define STG  65536
#define O_AHI 0
#define O_ALO 16384
#define O_BHI 32768
#define O_BLO 49152

__device__ __forceinline__ void issue_chunk(
    uint32_t sb_stage, const __nv_bfloat16* Ahi, const __nv_bfloat16* Alo,
    const __nv_bfloat16* Bhi, const __nv_bfloat16* Blo,
    int m0, int n0, int ch, int tid) {
#pragma unroll
  for (int r = 0; r < 4; r++) {
    int idx = tid + r * 256;
    int row = idx >> 3, q = idx & 7;
    uint32_t off = (uint32_t)(row << 7) + (q << 4);
    off ^= (off >> 3) & 0x70;
    size_t ga = ((size_t)(m0 + row) * DD + ch * KC + q * 8);
    size_t gb = ((size_t)(n0 + row) * DD + ch * KC + q * 8);
    cp16(sb_stage + O_AHI + off, Ahi + ga);
    cp16(sb_stage + O_ALO + off, Alo + ga);
    cp16(sb_stage + O_BHI + off, Bhi + gb);
    cp16(sb_stage + O_BLO + off, Blo + gb);
  }
}

__global__ void __launch_bounds__(256, 1)
k_mmagemm(const __nv_bfloat16* __restrict__ Ahi, const __nv_bfloat16* __restrict__ Alo,
          const __nv_bfloat16* __restrict__ Bhi, const __nv_bfloat16* __restrict__ Blo,
          float* __restrict__ C, const float* __restrict__ bias) {
  extern __shared__ char sm[];
  uint32_t sb = smem_u32(sm);
  int tid = threadIdx.x, lane = tid & 31, w = tid >> 5;
  int wm = (w & 3) * 32;        // warp M offset in tile
  int wn = (w >> 2) * 64;       // warp N offset in tile
  int m0 = blockIdx.y << 7, n0 = blockIdx.x << 7;

  float acc[2][8][4];
#pragma unroll
  for (int mt = 0; mt < 2; mt++)
#pragma unroll
    for (int nt = 0; nt < 8; nt++)
#pragma unroll
      for (int j = 0; j < 4; j++) acc[mt][nt][j] = 0.f;

  issue_chunk(sb, Ahi, Alo, Bhi, Blo, m0, n0, 0, tid);
  asm volatile("cp.async.commit_group;");

  const int NCH = DD / KC;   // 34
  for (int ch = 0; ch < NCH; ch++) {
    uint32_t cur = sb + (uint32_t)(ch & 1) * STG;
    if (ch + 1 < NCH) {
      issue_chunk(sb + (uint32_t)((ch + 1) & 1) * STG, Ahi, Alo, Bhi, Blo, m0, n0, ch + 1, tid);
      asm volatile("cp.async.commit_group;");
      asm volatile("cp.async.wait_group 1;");
    } else {
      asm volatile("cp.async.wait_group 0;");
    }
    __syncthreads();

#pragma unroll
    for (int ks = 0; ks < 4; ks++) {
      uint32_t ah[2][4], al[2][4];
#pragma unroll
      for (int mt = 0; mt < 2; mt++) {
        uint32_t row = wm + mt * 16 + (lane & 15);
        uint32_t off = (row << 7) + ks * 32 + ((lane >> 4) << 4);
        off ^= (off >> 3) & 0x70;
        ldsm4(cur + O_AHI + off, ah[mt][0], ah[mt][1], ah[mt][2], ah[mt][3]);
        ldsm4(cur + O_ALO + off, al[mt][0], al[mt][1], al[mt][2], al[mt][3]);
      }
      uint32_t bh[4][4], bl[4][4];
#pragma unroll
      for (int ng = 0; ng < 4; ng++) {
        uint32_t row = wn + ng * 16 + (lane & 15);
        uint32_t off = (row << 7) + ks * 32 + ((lane >> 4) << 4);
        off ^= (off >> 3) & 0x70;
        ldsm4(cur + O_BHI + off, bh[ng][0], bh[ng][1], bh[ng][2], bh[ng][3]);
        ldsm4(cur + O_BLO + off, bl[ng][0], bl[ng][1], bl[ng][2], bl[ng][3]);
      }
#pragma unroll
      for (int mt = 0; mt < 2; mt++)
#pragma unroll
        for (int ng = 0; ng < 4; ng++) {
          // n-tile 2*ng: frag {r0, r2}; n-tile 2*ng+1: frag {r1, r3}
          mma16816(acc[mt][ng*2],   ah[mt], bh[ng][0], bh[ng][2]);
          mma16816(acc[mt][ng*2+1], ah[mt], bh[ng][1], bh[ng][3]);
          mma16816(acc[mt][ng*2],   ah[mt], bl[ng][0], bl[ng][2]);
          mma16816(acc[mt][ng*2+1], ah[mt], bl[ng][1], bl[ng][3]);
          mma16816(acc[mt][ng*2],   al[mt], bh[ng][0], bh[ng][2]);
          mma16816(acc[mt][ng*2+1], al[mt], bh[ng][1], bh[ng][3]);
        }
    }
    __syncthreads();
  }

  // epilogue: c0,c1 -> row (lane>>2), cols (lane&3)*2,(+1); c2,c3 -> row+8
#pragma unroll
  for (int mt = 0; mt < 2; mt++) {
    int r = m0 + wm + mt * 16 + (lane >> 2);
#pragma unroll
    for (int nt = 0; nt < 8; nt++) {
      int cc = n0 + wn + nt * 8 + (lane & 3) * 2;
      float b0 = 0.f, b1 = 0.f;
      if (bias) { b0 = bias[cc]; b1 = bias[cc + 1]; }
      float2 v0 = make_float2(acc[mt][nt][0] + b0, acc[mt][nt][1] + b1);
      float2 v1 = make_float2(acc[mt][nt][2] + b0, acc[mt][nt][3] + b1);
      *(float2*)(C + (size_t)r * GG + cc) = v0;
      *(float2*)(C + (size_t)(r + 8) * GG + cc) = v1;
    }
  }
}

// ============================ LSTM ============================
__device__ __forceinline__ float sigf(float x) { return 1.f / (1.f + expf(-x)); }

__global__ void __launch_bounds__(256)
k_lstm_step(const float* __restrict__ pre_t, const float* __restrict__ h_in,
            float* __restrict__ h_out, float* __restrict__ c_st,
            const float* __restrict__ WhhT) {
  int b0 = blockIdx.x * 16;
  int j0 = blockIdx.y * 32;
  int tid = threadIdx.x;
  int jl = tid & 31;
  int bq = tid >> 5;
  __shared__ float hs[16][32];
  __shared__ float ws[32][128];
  float acc[2][4];
#pragma unroll
  for (int a = 0; a < 2; a++)
#pragma unroll
    for (int g = 0; g < 4; g++) acc[a][g] = 0.f;

  for (int k0 = 0; k0 < LH_; k0 += 32) {
#pragma unroll
    for (int r = 0; r < 2; r++) {
      int idx = tid + r * 256;
      int bl = idx >> 5, kk = idx & 31;
      hs[bl][kk] = h_in[(b0 + bl) * LH_ + k0 + kk];
    }
#pragma unroll
    for (int r = 0; r < 16; r++) {
      int idx = tid + r * 256;
      int kk = idx >> 7, col = idx & 127;
      int g = col >> 5, jj = col & 31;
      ws[kk][col] = WhhT[(size_t)(k0 + kk) * GG + g * 256 + j0 + jj];
    }
    __syncthreads();
#pragma unroll
    for (int kk = 0; kk < 32; kk++) {
      float a0 = hs[bq][kk], a1 = hs[bq + 8][kk];
#pragma unroll
      for (int g = 0; g < 4; g++) {
        float w = ws[kk][g*32 + jl];
        acc[0][g] += a0 * w;
        acc[1][g] += a1 * w;
      }
    }
    __syncthreads();
  }
#pragma unroll
  for (int a = 0; a < 2; a++) {
    int b = b0 + bq + a * 8;
    int j = j0 + jl;
    const float* pr = pre_t + (size_t)b * GG;
    float zi = acc[a][0] + pr[j];
    float zf = acc[a][1] + pr[256 + j];
    float zg = acc[a][2] + pr[512 + j];
    float zo = acc[a][3] + pr[768 + j];
    float co = c_st[b * LH_ + j];
    float cn = sigf(zf) * co + sigf(zi) * tanhf(zg);
    c_st[b * LH_ + j] = cn;
    h_out[b * LH_ + j] = sigf(zo) * tanhf(cn);
  }
}

__global__ void k_backstep(const float* __restrict__ bih, const float* __restrict__ bhh) {
  int b = blockIdx.x, j = threadIdx.x;
  const float* pr = g_preb + (size_t)b * GG;
  float zi = pr[j]       + bih[j]       + bhh[j];
  float zg = pr[512 + j] + bih[512 + j] + bhh[512 + j];
  float zo = pr[768 + j] + bih[768 + j] + bhh[768 + j];
  float cn = sigf(zi) * tanhf(zg);
  g_hbk[b * LH_ + j] = sigf(zo) * tanhf(cn);
}

__global__ void k_pool(const float* __restrict__ hf, float* outp) {
  int idx = blockIdx.x * 256 + threadIdx.x;
  int b = idx >> 9, d = idx & 511;
  float v = (d < 256) ? hf[b * 256 + d] : g_hbk[b * 256 + d - 256];
  v = fmaxf(v, 0.f);
  g_pool[idx] = v;
  if (outp) outp[idx] = v;
}

__global__ void k_cls(const float* __restrict__ Wc, const float* __restrict__ bc,
                      float* __restrict__ outc) {
  int b = blockIdx.x;
  int m = blockIdx.y * 128 + threadIdx.x;
  __shared__ float sp[512];
  int t = threadIdx.x;
  sp[t] = g_pool[b*512 + t]; sp[t+128] = g_pool[b*512 + t + 128];
  sp[t+256] = g_pool[b*512 + t + 256]; sp[t+384] = g_pool[b*512 + t + 384];
  __syncthreads();
  if (m < NC_) {
    float acc = bc[m];
    const float* wr = Wc + (size_t)m * 512;
    for (int d = 0; d < 512; d++) acc += sp[d] * wr[d];
    outc[(size_t)b * NC_ + m] = acc;
  }
}

// ============================ host ============================
extern "C" void kernel_launch(void* const* d_in, const int* in_sizes, int n_in,
                              void* d_out, int out_size) {
  const float* pose1 = (const float*)d_in[0];
  const float* pose2 = (const float*)d_in[1];
  const float* W1    = (const float*)d_in[2];
  const float* b1    = (const float*)d_in[3];
  const float* W2    = (const float*)d_in[4];
  const float* b2    = (const float*)d_in[5];
  const float* Wih_f = (const float*)d_in[6];
  const float* Whh_f = (const float*)d_in[7];
  const float* bih_f = (const float*)d_in[8];
  const float* bhh_f = (const float*)d_in[9];
  const float* Wih_b = (const float*)d_in[10];
  const float* Whh_b = (const float*)d_in[11];
  const float* bih_b = (const float*)d_in[12];
  const float* bhh_b = (const float*)d_in[13];
  const float* Wc    = (const float*)d_in[14];
  const float* bc    = (const float*)d_in[15];
  (void)Whh_b; (void)in_sizes; (void)n_in;
  float* out = (float*)d_out;

  void *pWihT, *pWhhT, *pV, *pPre, *pE, *pF, *pPreb, *pBias, *pHA, *pHB, *pC;
  void *pShi, *pSlo, *pVtHi, *pVtLo, *pWbHi, *pWbLo, *pEhi, *pElo, *pFhi, *pFlo, *pCorr, *pSlast;
  cudaGetSymbolAddress(&pWihT,  g_WihT);
  cudaGetSymbolAddress(&pWhhT,  g_WhhT);
  cudaGetSymbolAddress(&pV,     g_V);
  cudaGetSymbolAddress(&pPre,   g_pre);
  cudaGetSymbolAddress(&pE,     g_E);
  cudaGetSymbolAddress(&pF,     g_F);
  cudaGetSymbolAddress(&pPreb,  g_preb);
  cudaGetSymbolAddress(&pBias,  g_biasV);
  cudaGetSymbolAddress(&pHA,    g_hA);
  cudaGetSymbolAddress(&pHB,    g_hB);
  cudaGetSymbolAddress(&pC,     g_cst);
  cudaGetSymbolAddress(&pShi,   g_Shi);
  cudaGetSymbolAddress(&pSlo,   g_Slo);
  cudaGetSymbolAddress(&pVtHi,  g_VtHi);
  cudaGetSymbolAddress(&pVtLo,  g_VtLo);
  cudaGetSymbolAddress(&pWbHi,  g_WbHi);
  cudaGetSymbolAddress(&pWbLo,  g_WbLo);
  cudaGetSymbolAddress(&pEhi,   g_Ehi);
  cudaGetSymbolAddress(&pElo,   g_Elo);
  cudaGetSymbolAddress(&pFhi,   g_Fhi);
  cudaGetSymbolAddress(&pFlo,   g_Flo);
  cudaGetSymbolAddress(&pCorr,  g_corr);
  cudaGetSymbolAddress(&pSlast, g_Slast);

  float* pool_dst = nullptr;
  float* cls_dst  = nullptr;
  if (out_size == B_*512 + B_*NC_)      { pool_dst = out; cls_dst = out + B_*512; }
  else if (out_size == B_*NC_)          { cls_dst = out; }
  else if (out_size == B_*512)          { pool_dst = out; }
  else { pool_dst = out; if (out_size >= B_*512 + B_*NC_) cls_dst = out + B_*512; }

  cudaFuncSetAttribute(k_mmagemm, cudaFuncAttributeMaxDynamicSharedMemorySize, 2*STG);

  k_init_ahat<<<1, 32>>>();
  k_transpose<<<(GG*DD + 255)/256, 256>>>(Wih_f, (float*)pWihT, GG, DD);
  k_biasV<<<GG, 256>>>(Wih_f, bih_f, bhh_f, b2);
  k_split<<<(GG*DD/4 + 255)/256, 256>>>(Wih_b, (__nv_bfloat16*)pWbHi, (__nv_bfloat16*)pWbLo, GG*DD/4);

  // V fold: V_i = W2 @ WihT_f[i] (17 batched 128x1024), then transpose+split -> Vt
  k_sgemm<<<dim3(8, 1, 17), 256>>>(128, GG, 128, W2, (const float*)pWihT, (float*)pV,
                                   nullptr, 0LL, (long long)128*GG, (long long)128*GG);
  k_tsplit<<<dim3(GG/32, DD/32), 256>>>((const float*)pV, (__nv_bfloat16*)pVtHi, (__nv_bfloat16*)pVtLo);

  // GCN layer 1 -> S split (+H10, Slast); E = 0.5*(A-I)@H10; split E
  k_layer1<<<T_*B_, 128>>>(pose1, pose2, W1, b1);
  k_E<<<T_, 128>>>();
  k_split<<<(T_*DD/4 + 255)/256, 256>>>((const float*)pE, (__nv_bfloat16*)pEhi, (__nv_bfloat16*)pElo, T_*DD/4);

  // pre = S @ V + biasV   (tensor-core split-bf16, 146 GFLOP x3)
  k_mmagemm<<<dim3(8, 256), 256, 2*STG>>>((const __nv_bfloat16*)pShi, (const __nv_bfloat16*)pSlo,
                                          (const __nv_bfloat16*)pVtHi, (const __nv_bfloat16*)pVtLo,
                                          (float*)pPre, (const float*)pBias);
  // corr = E @ V ; pre[t, b=0, :] += corr[t]
  k_mmagemm<<<dim3(8, 2), 256, 2*STG>>>((const __nv_bfloat16*)pEhi, (const __nv_bfloat16*)pElo,
                                        (const __nv_bfloat16*)pVtHi, (const __nv_bfloat16*)pVtLo,
                                        (float*)pCorr, nullptr);
  k_addcorr<<<(T_*GG)/256, 256>>>();

  // backward: F = Slast @ W2 + b2; fix b=0; pre_b = F @ Wih_b^T
  k_sgemm<<<dim3(1, (B_*NN)/128, 1), 256>>>(B_*NN, 128, 128, (const float*)pSlast, W2,
                                            (float*)pF, b2, 0LL, 0LL, 0LL);
  k_fixF0<<<NN, 128>>>(W2);
  k_split<<<(B_*DD/4 + 255)/256, 256>>>((const float*)pF, (__nv_bfloat16*)pFhi, (__nv_bfloat16*)pFlo, B_*DD/4);
  k_mmagemm<<<dim3(8, 1), 256, 2*STG>>>((const __nv_bfloat16*)pFhi, (const __nv_bfloat16*)pFlo,
                                        (const __nv_bfloat16*)pWbHi, (const __nv_bfloat16*)pWbLo,
                                        (float*)pPreb, nullptr);

  // transpose Whh_f for the step kernel
  k_transpose<<<(GG*LH_ + 255)/256, 256>>>(Whh_f, (float*)pWhhT, GG, LH_);

  // forward recurrence
  cudaMemsetAsync(pHA, 0, (size_t)B_ * LH_ * sizeof(float));
  cudaMemsetAsync(pC,  0, (size_t)B_ * LH_ * sizeof(float));
  float* hin = (float*)pHA;
  float* hout = (float*)pHB;
  for (int t = 0; t < T_; t++) {
    k_lstm_step<<<dim3(B_/16, LH_/32), 256>>>((const float*)pPre + (size_t)t * B_ * GG,
                                              hin, hout, (float*)pC, (const float*)pWhhT);
    float* tmp = hin; hin = hout; hout = tmp;
  }

  k_backstep<<<B_, 256>>>(bih_b, bhh_b);
  k_pool<<<(B_*512)/256, 256>>>(hin, pool_dst);
  if (cls_dst) k_cls<<<dim3(B_, 5), 128>>>(Wc, bc, cls_dst);
}

// round 15
// speedup vs baseline: 2.2551x; 1.4069x over previous
#include <cuda_runtime.h>
#include <cuda_bf16.h>
#include <math.h>
#include <stdint.h>

#define T_  256
#define B_  128
#define NN  17
#define DD  2176   // 17*128
#define GG  1024   // 4*256
#define LH_ 256
#define NC_ 625
#define LCTA 32    // persistent LSTM CTAs

__constant__ int c_conn[19][2] = {
  {15,13},{13,11},{16,14},{14,12},{11,12},{5,11},{6,12},{5,6},{5,7},{6,8},
  {7,9},{8,10},{1,2},{0,1},{0,2},{1,3},{2,4},{3,5},{4,6}
};

// ---- scratch (device globals) ----
__device__ float g_AHAT[NN*NN];
__device__ float g_AmI[NN*NN];
__device__ __nv_bfloat16 g_Shi[(size_t)T_*B_*DD];
__device__ __nv_bfloat16 g_Slo[(size_t)T_*B_*DD];
__device__ float g_Slast[(size_t)B_*DD];
__device__ float g_H10[(size_t)T_*NN*128];
__device__ float g_E[(size_t)T_*DD];
__device__ __nv_bfloat16 g_Ehi[(size_t)T_*DD];
__device__ __nv_bfloat16 g_Elo[(size_t)T_*DD];
__device__ float g_V[(size_t)DD*GG];
__device__ __nv_bfloat16 g_VtHi[(size_t)GG*DD];
__device__ __nv_bfloat16 g_VtLo[(size_t)GG*DD];
__device__ __nv_bfloat16 g_WbHi[(size_t)GG*DD];
__device__ __nv_bfloat16 g_WbLo[(size_t)GG*DD];
__device__ float g_WihT[(size_t)DD*GG];
__device__ float g_biasV[GG];
__device__ float g_pre[(size_t)T_*B_*GG];
__device__ float g_corr[(size_t)T_*GG];
__device__ float g_F[(size_t)B_*DD];
__device__ __nv_bfloat16 g_Fhi[(size_t)B_*DD];
__device__ __nv_bfloat16 g_Flo[(size_t)B_*DD];
__device__ float g_preb[(size_t)B_*GG];
__device__ float g_hA[B_*LH_];
__device__ float g_hbk[B_*LH_];
__device__ float g_pool[B_*512];
// persistent LSTM state
__device__ unsigned g_barcnt;
__device__ __nv_bfloat16 g_hhi[2][B_*LH_];
__device__ __nv_bfloat16 g_hlo[2][B_*LH_];

// ============================ helpers ============================
__device__ __forceinline__ uint32_t smem_u32(const void* p) {
  uint32_t a;
  asm("{ .reg .u64 t; cvta.to.shared.u64 t, %1; cvt.u32.u64 %0, t; }" : "=r"(a) : "l"(p));
  return a;
}
__device__ __forceinline__ void cp16(uint32_t saddr, const void* g) {
  asm volatile("cp.async.cg.shared.global [%0], [%1], 16;" :: "r"(saddr), "l"(g));
}
__device__ __forceinline__ void ldsm4(uint32_t addr, uint32_t& r0, uint32_t& r1,
                                      uint32_t& r2, uint32_t& r3) {
  asm volatile("ldmatrix.sync.aligned.m8n8.x4.shared.b16 {%0,%1,%2,%3}, [%4];"
               : "=r"(r0), "=r"(r1), "=r"(r2), "=r"(r3) : "r"(addr));
}
__device__ __forceinline__ void mma16816(float* c, const uint32_t* a, uint32_t b0, uint32_t b1) {
  asm volatile(
    "mma.sync.aligned.m16n8k16.row.col.f32.bf16.bf16.f32 "
    "{%0,%1,%2,%3}, {%4,%5,%6,%7}, {%8,%9}, {%0,%1,%2,%3};"
    : "+f"(c[0]), "+f"(c[1]), "+f"(c[2]), "+f"(c[3])
    : "r"(a[0]), "r"(a[1]), "r"(a[2]), "r"(a[3]), "r"(b0), "r"(b1));
}

// ============================ setup kernels ============================
__global__ void k_init_ahat() {
  if (threadIdx.x != 0 || blockIdx.x != 0) return;
  double deg[NN];
  for (int i = 0; i < NN; i++) deg[i] = 1.0;
  for (int e = 0; e < 19; e++) deg[c_conn[e][1]] += 1.0;
  double dis[NN];
  for (int i = 0; i < NN; i++) dis[i] = 1.0 / sqrt(deg[i]);
  double A[NN][NN];
  for (int i = 0; i < NN; i++) for (int j = 0; j < NN; j++) A[i][j] = 0.0;
  for (int e = 0; e < 19; e++) {
    int s = c_conn[e][0], d = c_conn[e][1];
    A[d][s] += dis[s] * dis[d];
  }
  for (int i = 0; i < NN; i++) A[i][i] += dis[i] * dis[i];
  for (int i = 0; i < NN; i++) for (int j = 0; j < NN; j++) {
    float v = (float)A[i][j];
    g_AHAT[i*NN+j] = v;
    g_AmI[i*NN+j]  = v - (i == j ? 1.f : 0.f);
  }
}

__global__ void k_transpose(const float* __restrict__ in, float* __restrict__ out, int R, int C) {
  int idx = blockIdx.x * 256 + threadIdx.x;
  if (idx < R * C) {
    int r = idx / C, c = idx - r * C;
    out[(size_t)c * R + r] = in[idx];
  }
}

__global__ void k_split(const float* __restrict__ in, __nv_bfloat16* __restrict__ hi,
                        __nv_bfloat16* __restrict__ lo, int n4) {
  int i = blockIdx.x * 256 + threadIdx.x;
  if (i >= n4) return;
  float4 v = ((const float4*)in)[i];
  __nv_bfloat16 hx = __float2bfloat16(v.x), hy = __float2bfloat16(v.y);
  __nv_bfloat16 hz = __float2bfloat16(v.z), hw = __float2bfloat16(v.w);
  __nv_bfloat16 lx = __float2bfloat16(v.x - __bfloat162float(hx));
  __nv_bfloat16 ly = __float2bfloat16(v.y - __bfloat162float(hy));
  __nv_bfloat16 lz = __float2bfloat16(v.z - __bfloat162float(hz));
  __nv_bfloat16 lw = __float2bfloat16(v.w - __bfloat162float(hw));
  __nv_bfloat162* H = (__nv_bfloat162*)hi;
  __nv_bfloat162* L = (__nv_bfloat162*)lo;
  H[2*i]   = __halves2bfloat162(hx, hy);
  H[2*i+1] = __halves2bfloat162(hz, hw);
  L[2*i]   = __halves2bfloat162(lx, ly);
  L[2*i+1] = __halves2bfloat162(lz, lw);
}

// transpose+split: in [DD][GG] fp32 -> out [GG][DD] bf16 hi/lo
__global__ void k_tsplit(const float* __restrict__ in, __nv_bfloat16* __restrict__ hi,
                         __nv_bfloat16* __restrict__ lo) {
  __shared__ float t[32][33];
  int bx = blockIdx.x;
  int by = blockIdx.y;
  int tx = threadIdx.x & 31, ty = threadIdx.x >> 5;
#pragma unroll
  for (int j = 0; j < 4; j++)
    t[ty + j*8][tx] = in[(size_t)(by*32 + ty + j*8) * GG + bx*32 + tx];
  __syncthreads();
#pragma unroll
  for (int j = 0; j < 4; j++) {
    float v = t[tx][ty + j*8];
    size_t o = (size_t)(bx*32 + ty + j*8) * DD + by*32 + tx;
    __nv_bfloat16 h = __float2bfloat16(v);
    hi[o] = h;
    lo[o] = __float2bfloat16(v - __bfloat162float(h));
  }
}

__global__ void k_biasV(const float* __restrict__ Wih, const float* __restrict__ bih,
                        const float* __restrict__ bhh, const float* __restrict__ b2) {
  int n = blockIdx.x;
  float acc = 0.f;
  const float* row = Wih + (size_t)n * DD;
  for (int ic = threadIdx.x; ic < DD; ic += 256) acc += b2[ic & 127] * row[ic];
  __shared__ float r[256];
  r[threadIdx.x] = acc;
  __syncthreads();
  for (int s = 128; s > 0; s >>= 1) {
    if (threadIdx.x < s) r[threadIdx.x] += r[threadIdx.x + s];
    __syncthreads();
  }
  if (threadIdx.x == 0) g_biasV[n] = r[0] + bih[n] + bhh[n];
}

// ---- generic SIMT SGEMM (small folds only) ----
__global__ void __launch_bounds__(256, 2)
k_sgemm(int M, int N, int K,
        const float* __restrict__ A, const float* __restrict__ B,
        float* __restrict__ C, const float* __restrict__ bias,
        long long sA, long long sB, long long sC) {
  A += (size_t)blockIdx.z * (size_t)sA;
  B += (size_t)blockIdx.z * (size_t)sB;
  C += (size_t)blockIdx.z * (size_t)sC;
  __shared__ float As[8][128];
  __shared__ float Bs[8][128];
  int tid = threadIdx.x;
  int m0 = blockIdx.y * 128, n0 = blockIdx.x * 128;
  int tx = tid & 15, ty = tid >> 4;
  int arow = tid >> 1, ak = (tid & 1) << 2;
  int bk = tid >> 5, bn = (tid & 31) << 2;
  float acc[8][8];
#pragma unroll
  for (int i = 0; i < 8; i++)
#pragma unroll
    for (int j = 0; j < 8; j++) acc[i][j] = 0.f;

  for (int k0 = 0; k0 < K; k0 += 8) {
    float4 av = make_float4(0.f, 0.f, 0.f, 0.f);
    if (m0 + arow < M) av = *(const float4*)(A + (size_t)(m0 + arow) * K + k0 + ak);
    float4 bv = make_float4(0.f, 0.f, 0.f, 0.f);
    if (n0 + bn < N) bv = *(const float4*)(B + (size_t)(k0 + bk) * N + n0 + bn);
    __syncthreads();
    As[ak+0][arow] = av.x; As[ak+1][arow] = av.y;
    As[ak+2][arow] = av.z; As[ak+3][arow] = av.w;
    *(float4*)&Bs[bk][bn] = bv;
    __syncthreads();
#pragma unroll
    for (int kk = 0; kk < 8; kk++) {
      float a[8], b[8];
      *(float4*)&a[0] = *(const float4*)&As[kk][ty*8];
      *(float4*)&a[4] = *(const float4*)&As[kk][ty*8+4];
      *(float4*)&b[0] = *(const float4*)&Bs[kk][tx*8];
      *(float4*)&b[4] = *(const float4*)&Bs[kk][tx*8+4];
#pragma unroll
      for (int i = 0; i < 8; i++)
#pragma unroll
        for (int j = 0; j < 8; j++) acc[i][j] += a[i] * b[j];
    }
  }
#pragma unroll
  for (int i = 0; i < 8; i++) {
    int m = m0 + ty*8 + i;
    if (m >= M) continue;
    float* cp = C + (size_t)m * N + n0 + tx*8;
#pragma unroll
    for (int j = 0; j < 8; j++) {
      float v = acc[i][j];
      if (bias) v += bias[n0 + tx*8 + j];
      cp[j] = v;
    }
  }
}

// ---- GCN layer 1 ----
__global__ void k_layer1(const float* __restrict__ pose1, const float* __restrict__ pose2,
                         const float* __restrict__ W1, const float* __restrict__ b1) {
  int bid = blockIdx.x;
  int c = threadIdx.x;
  int b = bid & 127, t = bid >> 7;
  __shared__ float sp1[NN*3], sp2[NN*3];
  __shared__ float sg[NN*128];
  size_t pbase = ((size_t)b * T_ + t) * NN * 3;
  if (c < NN*3) { sp1[c] = pose1[pbase + c]; sp2[c] = pose2[pbase + c]; }
  __syncthreads();
  float w0 = W1[c], w1 = W1[128 + c], w2 = W1[256 + c];
  float bb = b1[c];
  size_t srow = ((size_t)t * B_ + b) * NN;
  for (int i = 0; i < NN; i++) {
    float v1, v2;
    if (b == 0) {
      if (i == 0) {
        for (int ii = 0; ii < NN; ii++)
          sg[ii*128 + c] = sp1[ii*3]*w0 + sp1[ii*3+1]*w1 + sp1[ii*3+2]*w2;
        __syncthreads();
      }
      float agg = 0.f;
      for (int j = 0; j < NN; j++) agg += g_AHAT[i*NN+j] * sg[j*128 + c];
      v1 = fmaxf(agg + bb, 0.f);
      g_H10[((size_t)t*NN + i)*128 + c] = v1;
    } else {
      v1 = fmaxf(sp1[i*3]*w0 + sp1[i*3+1]*w1 + sp1[i*3+2]*w2 + bb, 0.f);
    }
    v2 = fmaxf(sp2[i*3]*w0 + sp2[i*3+1]*w1 + sp2[i*3+2]*w2 + bb, 0.f);
    float s = 0.5f * (v1 + v2);
    size_t o = (srow + i) * 128 + c;
    __nv_bfloat16 h = __float2bfloat16(s);
    g_Shi[o] = h;
    g_Slo[o] = __float2bfloat16(s - __bfloat162float(h));
    if (t == T_-1) g_Slast[((size_t)b*NN + i)*128 + c] = s;
  }
}

__global__ void k_E() {
  int t = blockIdx.x, c = threadIdx.x;
  __shared__ float sh[NN*128];
  for (int i = 0; i < NN; i++) sh[i*128 + c] = g_H10[((size_t)t*NN + i)*128 + c];
  __syncthreads();
  for (int i = 0; i < NN; i++) {
    float acc = 0.f;
    for (int j = 0; j < NN; j++) acc += g_AmI[i*NN+j] * sh[j*128 + c];
    g_E[((size_t)t*NN + i)*128 + c] = 0.5f * acc;
  }
}

__global__ void k_addcorr() {
  int idx = blockIdx.x * 256 + threadIdx.x;
  int t = idx >> 10, n = idx & 1023;
  g_pre[(size_t)t * B_ * GG + n] += g_corr[idx];
}

__global__ void k_fixF0(const float* __restrict__ W2) {
  int i = blockIdx.x, cc = threadIdx.x;
  __shared__ float se[128];
  se[cc] = g_E[((size_t)(T_-1)*NN + i)*128 + cc];
  __syncthreads();
  float acc = 0.f;
  for (int k = 0; k < 128; k++) acc += se[k] * W2[k*128 + cc];
  g_F[i*128 + cc] += acc;
}

// ============================ mma.sync split-bf16 GEMM ============================
#define KC   64
#define STG  65536
#define O_AHI 0
#define O_ALO 16384
#define O_BHI 32768
#define O_BLO 49152

__device__ __forceinline__ void issue_chunk(
    uint32_t sb_stage, const __nv_bfloat16* Ahi, const __nv_bfloat16* Alo,
    const __nv_bfloat16* Bhi, const __nv_bfloat16* Blo,
    int m0, int n0, int ch, int tid) {
#pragma unroll
  for (int r = 0; r < 4; r++) {
    int idx = tid + r * 256;
    int row = idx >> 3, q = idx & 7;
    uint32_t off = (uint32_t)(row << 7) + (q << 4);
    off ^= (off >> 3) & 0x70;
    size_t ga = ((size_t)(m0 + row) * DD + ch * KC + q * 8);
    size_t gb = ((size_t)(n0 + row) * DD + ch * KC + q * 8);
    cp16(sb_stage + O_AHI + off, Ahi + ga);
    cp16(sb_stage + O_ALO + off, Alo + ga);
    cp16(sb_stage + O_BHI + off, Bhi + gb);
    cp16(sb_stage + O_BLO + off, Blo + gb);
  }
}

__global__ void __launch_bounds__(256, 1)
k_mmagemm(const __nv_bfloat16* __restrict__ Ahi, const __nv_bfloat16* __restrict__ Alo,
          const __nv_bfloat16* __restrict__ Bhi, const __nv_bfloat16* __restrict__ Blo,
          float* __restrict__ C, const float* __restrict__ bias) {
  extern __shared__ char sm[];
  uint32_t sb = smem_u32(sm);
  int tid = threadIdx.x, lane = tid & 31, w = tid >> 5;
  int wm = (w & 3) * 32;
  int wn = (w >> 2) * 64;
  int m0 = blockIdx.y << 7, n0 = blockIdx.x << 7;

  float acc[2][8][4];
#pragma unroll
  for (int mt = 0; mt < 2; mt++)
#pragma unroll
    for (int nt = 0; nt < 8; nt++)
#pragma unroll
      for (int j = 0; j < 4; j++) acc[mt][nt][j] = 0.f;

  issue_chunk(sb, Ahi, Alo, Bhi, Blo, m0, n0, 0, tid);
  asm volatile("cp.async.commit_group;");

  const int NCH = DD / KC;   // 34
  for (int ch = 0; ch < NCH; ch++) {
    uint32_t cur = sb + (uint32_t)(ch & 1) * STG;
    if (ch + 1 < NCH) {
      issue_chunk(sb + (uint32_t)((ch + 1) & 1) * STG, Ahi, Alo, Bhi, Blo, m0, n0, ch + 1, tid);
      asm volatile("cp.async.commit_group;");
      asm volatile("cp.async.wait_group 1;");
    } else {
      asm volatile("cp.async.wait_group 0;");
    }
    __syncthreads();

#pragma unroll
    for (int ks = 0; ks < 4; ks++) {
      uint32_t ah[2][4], al[2][4];
#pragma unroll
      for (int mt = 0; mt < 2; mt++) {
        uint32_t row = wm + mt * 16 + (lane & 15);
        uint32_t off = (row << 7) + ks * 32 + ((lane >> 4) << 4);
        off ^= (off >> 3) & 0x70;
        ldsm4(cur + O_AHI + off, ah[mt][0], ah[mt][1], ah[mt][2], ah[mt][3]);
        ldsm4(cur + O_ALO + off, al[mt][0], al[mt][1], al[mt][2], al[mt][3]);
      }
      uint32_t bh[4][4], bl[4][4];
#pragma unroll
      for (int ng = 0; ng < 4; ng++) {
        uint32_t row = wn + ng * 16 + (lane & 15);
        uint32_t off = (row << 7) + ks * 32 + ((lane >> 4) << 4);
        off ^= (off >> 3) & 0x70;
        ldsm4(cur + O_BHI + off, bh[ng][0], bh[ng][1], bh[ng][2], bh[ng][3]);
        ldsm4(cur + O_BLO + off, bl[ng][0], bl[ng][1], bl[ng][2], bl[ng][3]);
      }
#pragma unroll
      for (int mt = 0; mt < 2; mt++)
#pragma unroll
        for (int ng = 0; ng < 4; ng++) {
          mma16816(acc[mt][ng*2],   ah[mt], bh[ng][0], bh[ng][2]);
          mma16816(acc[mt][ng*2+1], ah[mt], bh[ng][1], bh[ng][3]);
          mma16816(acc[mt][ng*2],   ah[mt], bl[ng][0], bl[ng][2]);
          mma16816(acc[mt][ng*2+1], ah[mt], bl[ng][1], bl[ng][3]);
          mma16816(acc[mt][ng*2],   al[mt], bh[ng][0], bh[ng][2]);
          mma16816(acc[mt][ng*2+1], al[mt], bh[ng][1], bh[ng][3]);
        }
    }
    __syncthreads();
  }

#pragma unroll
  for (int mt = 0; mt < 2; mt++) {
    int r = m0 + wm + mt * 16 + (lane >> 2);
#pragma unroll
    for (int nt = 0; nt < 8; nt++) {
      int cc = n0 + wn + nt * 8 + (lane & 3) * 2;
      float b0 = 0.f, b1 = 0.f;
      if (bias) { b0 = bias[cc]; b1 = bias[cc + 1]; }
      float2 v0 = make_float2(acc[mt][nt][0] + b0, acc[mt][nt][1] + b1);
      float2 v1 = make_float2(acc[mt][nt][2] + b0, acc[mt][nt][3] + b1);
      *(float2*)(C + (size_t)r * GG + cc) = v0;
      *(float2*)(C + (size_t)(r + 8) * GG + cc) = v1;
    }
  }
}

// ============================ persistent fused forward LSTM ============================
// 32 CTAs; CTA jb owns hidden cols j = jb*8..jb*8+7 (all 4 gates); c-state in registers.
#define L_OBHI 0
#define L_OBLO 16384
#define L_OAHI 32768
#define L_OALO 98304
#define L_SMEM 163840

__device__ __forceinline__ float sigf(float x) { return 1.f / (1.f + expf(-x)); }

__global__ void __launch_bounds__(256, 1)
k_lstm_persist(const float* __restrict__ pre, const float* __restrict__ Whh,
               float* __restrict__ hfin) {
  extern __shared__ char sm[];
  uint32_t sb = smem_u32(sm);
  int tid = threadIdx.x, lane = tid & 31, w = tid >> 5;
  int jb = blockIdx.x;

  // preload Whh slice: smem row (g*8+jj) <- global row g*256 + jb*8 + jj; 256 k, split+swizzle
  for (int idx = tid; idx < 32 * 32; idx += 256) {
    int row = idx >> 5, q32 = idx & 31;
    int kc = q32 >> 3, q = q32 & 7;
    int g = row >> 3, jj = row & 7;
    const float* src = Whh + (size_t)(g * 256 + jb * 8 + jj) * LH_ + q32 * 8;
    float vv[8];
    *(float4*)&vv[0] = *(const float4*)src;
    *(float4*)&vv[4] = *(const float4*)(src + 4);
    __nv_bfloat16 h8[8], l8[8];
#pragma unroll
    for (int e = 0; e < 8; e++) {
      h8[e] = __float2bfloat16(vv[e]);
      l8[e] = __float2bfloat16(vv[e] - __bfloat162float(h8[e]));
    }
    uint32_t off = (uint32_t)(row << 7) + (q << 4);
    off ^= (off >> 3) & 0x70;
    *(float4*)(sm + L_OBHI + kc * 4096 + off) = *(float4*)h8;
    *(float4*)(sm + L_OBLO + kc * 4096 + off) = *(float4*)l8;
  }
  float c4[4] = {0.f, 0.f, 0.f, 0.f};
  __syncthreads();

  int r0 = w * 16 + (lane >> 2);
  int j  = jb * 8 + (lane & 3) * 2;

#pragma unroll 1
  for (int t = 0; t < T_; t++) {
    if (t > 0) {
      if (tid == 0) {
        volatile unsigned* p = &g_barcnt;
        while (*p < (unsigned)(LCTA * t)) { }
      }
      __syncthreads();
      __threadfence();
    }
    const __nv_bfloat16* Hh = g_hhi[t & 1];
    const __nv_bfloat16* Hl = g_hlo[t & 1];
    // load full h (128x256) split into swizzled smem
#pragma unroll
    for (int r = 0; r < 16; r++) {
      int idx = tid + r * 256;
      int row = idx >> 5, q32 = idx & 31;
      int kc = q32 >> 3, q = q32 & 7;
      uint32_t off = (uint32_t)(row << 7) + (q << 4);
      off ^= (off >> 3) & 0x70;
      cp16(sb + L_OAHI + kc * 16384 + off, Hh + row * LH_ + q32 * 8);
      cp16(sb + L_OALO + kc * 16384 + off, Hl + row * LH_ + q32 * 8);
    }
    asm volatile("cp.async.commit_group;");
    asm volatile("cp.async.wait_group 0;");
    __syncthreads();

    float acc[4][4];
#pragma unroll
    for (int g = 0; g < 4; g++)
#pragma unroll
      for (int e = 0; e < 4; e++) acc[g][e] = 0.f;

#pragma unroll 1
    for (int kc = 0; kc < 4; kc++) {
      uint32_t abase  = sb + L_OAHI + kc * 16384;
      uint32_t abase2 = sb + L_OALO + kc * 16384;
      uint32_t bbase  = sb + L_OBHI + kc * 4096;
      uint32_t bbase2 = sb + L_OBLO + kc * 4096;
#pragma unroll
      for (int ks = 0; ks < 4; ks++) {
        uint32_t ah[4], al[4];
        {
          uint32_t row = w * 16 + (lane & 15);
          uint32_t off = (row << 7) + ks * 32 + ((lane >> 4) << 4);
          off ^= (off >> 3) & 0x70;
          ldsm4(abase + off, ah[0], ah[1], ah[2], ah[3]);
          ldsm4(abase2 + off, al[0], al[1], al[2], al[3]);
        }
        uint32_t bh[2][4], bl[2][4];
#pragma unroll
        for (int ng = 0; ng < 2; ng++) {
          uint32_t row = ng * 16 + (lane & 15);
          uint32_t off = (row << 7) + ks * 32 + ((lane >> 4) << 4);
          off ^= (off >> 3) & 0x70;
          ldsm4(bbase + off, bh[ng][0], bh[ng][1], bh[ng][2], bh[ng][3]);
          ldsm4(bbase2 + off, bl[ng][0], bl[ng][1], bl[ng][2], bl[ng][3]);
        }
#pragma unroll
        for (int ng = 0; ng < 2; ng++) {
          mma16816(acc[ng*2],   ah, bh[ng][0], bh[ng][2]);
          mma16816(acc[ng*2+1], ah, bh[ng][1], bh[ng][3]);
          mma16816(acc[ng*2],   ah, bl[ng][0], bl[ng][2]);
          mma16816(acc[ng*2+1], ah, bl[ng][1], bl[ng][3]);
          mma16816(acc[ng*2],   al, bh[ng][0], bh[ng][2]);
          mma16816(acc[ng*2+1], al, bh[ng][1], bh[ng][3]);
        }
      }
    }

    // epilogue: z = acc + pre[t,b,g*256+jc]; update c, h
    const float* pb = pre + (size_t)t * B_ * GG;
    __nv_bfloat16* Whi = g_hhi[(t + 1) & 1];
    __nv_bfloat16* Wlo = g_hlo[(t + 1) & 1];
#pragma unroll
    for (int e = 0; e < 4; e++) {
      int b = r0 + (e >> 1) * 8;
      int jc = j + (e & 1);
      const float* pr = pb + (size_t)b * GG + jc;
      float zi = acc[0][e] + pr[0];
      float zf = acc[1][e] + pr[256];
      float zg = acc[2][e] + pr[512];
      float zo = acc[3][e] + pr[768];
      float cn = sigf(zf) * c4[e] + sigf(zi) * tanhf(zg);
      c4[e] = cn;
      float hv = sigf(zo) * tanhf(cn);
      __nv_bfloat16 hh = __float2bfloat16(hv);
      Whi[b * LH_ + jc] = hh;
      Wlo[b * LH_ + jc] = __float2bfloat16(hv - __bfloat162float(hh));
      if (t == T_ - 1) hfin[b * LH_ + jc] = hv;
    }
    __threadfence();
    __syncthreads();
    if (tid == 0) atomicAdd(&g_barcnt, 1u);
  }
}

// ============================ tail kernels ============================
__global__ void k_backstep(const float* __restrict__ bih, const float* __restrict__ bhh) {
  int b = blockIdx.x, jx = threadIdx.x;
  const float* pr = g_preb + (size_t)b * GG;
  float zi = pr[jx]       + bih[jx]       + bhh[jx];
  float zg = pr[512 + jx] + bih[512 + jx] + bhh[512 + jx];
  float zo = pr[768 + jx] + bih[768 + jx] + bhh[768 + jx];
  float cn = sigf(zi) * tanhf(zg);
  g_hbk[b * LH_ + jx] = sigf(zo) * tanhf(cn);
}

__global__ void k_pool(const float* __restrict__ hf, float* outp) {
  int idx = blockIdx.x * 256 + threadIdx.x;
  int b = idx >> 9, d = idx & 511;
  float v = (d < 256) ? hf[b * 256 + d] : g_hbk[b * 256 + d - 256];
  v = fmaxf(v, 0.f);
  g_pool[idx] = v;
  if (outp) outp[idx] = v;
}

__global__ void k_cls(const float* __restrict__ Wc, const float* __restrict__ bc,
                      float* __restrict__ outc) {
  int b = blockIdx.x;
  int m = blockIdx.y * 128 + threadIdx.x;
  __shared__ float sp[512];
  int t = threadIdx.x;
  sp[t] = g_pool[b*512 + t]; sp[t+128] = g_pool[b*512 + t + 128];
  sp[t+256] = g_pool[b*512 + t + 256]; sp[t+384] = g_pool[b*512 + t + 384];
  __syncthreads();
  if (m < NC_) {
    float acc = bc[m];
    const float* wr = Wc + (size_t)m * 512;
    for (int d = 0; d < 512; d++) acc += sp[d] * wr[d];
    outc[(size_t)b * NC_ + m] = acc;
  }
}

// ============================ host ============================
extern "C" void kernel_launch(void* const* d_in, const int* in_sizes, int n_in,
                              void* d_out, int out_size) {
  const float* pose1 = (const float*)d_in[0];
  const float* pose2 = (const float*)d_in[1];
  const float* W1    = (const float*)d_in[2];
  const float* b1    = (const float*)d_in[3];
  const float* W2    = (const float*)d_in[4];
  const float* b2    = (const float*)d_in[5];
  const float* Wih_f = (const float*)d_in[6];
  const float* Whh_f = (const float*)d_in[7];
  const float* bih_f = (const float*)d_in[8];
  const float* bhh_f = (const float*)d_in[9];
  const float* Wih_b = (const float*)d_in[10];
  const float* Whh_b = (const float*)d_in[11];
  const float* bih_b = (const float*)d_in[12];
  const float* bhh_b = (const float*)d_in[13];
  const float* Wc    = (const float*)d_in[14];
  const float* bc    = (const float*)d_in[15];
  (void)Whh_b; (void)in_sizes; (void)n_in;
  float* out = (float*)d_out;

  void *pWihT, *pV, *pPre, *pE, *pF, *pPreb, *pBias, *pHA;
  void *pShi, *pSlo, *pVtHi, *pVtLo, *pWbHi, *pWbLo, *pEhi, *pElo, *pFhi, *pFlo, *pCorr, *pSlast;
  void *pBar, *pHhi, *pHlo;
  cudaGetSymbolAddress(&pWihT,  g_WihT);
  cudaGetSymbolAddress(&pV,     g_V);
  cudaGetSymbolAddress(&pPre,   g_pre);
  cudaGetSymbolAddress(&pE,     g_E);
  cudaGetSymbolAddress(&pF,     g_F);
  cudaGetSymbolAddress(&pPreb,  g_preb);
  cudaGetSymbolAddress(&pBias,  g_biasV);
  cudaGetSymbolAddress(&pHA,    g_hA);
  cudaGetSymbolAddress(&pShi,   g_Shi);
  cudaGetSymbolAddress(&pSlo,   g_Slo);
  cudaGetSymbolAddress(&pVtHi,  g_VtHi);
  cudaGetSymbolAddress(&pVtLo,  g_VtLo);
  cudaGetSymbolAddress(&pWbHi,  g_WbHi);
  cudaGetSymbolAddress(&pWbLo,  g_WbLo);
  cudaGetSymbolAddress(&pEhi,   g_Ehi);
  cudaGetSymbolAddress(&pElo,   g_Elo);
  cudaGetSymbolAddress(&pFhi,   g_Fhi);
  cudaGetSymbolAddress(&pFlo,   g_Flo);
  cudaGetSymbolAddress(&pCorr,  g_corr);
  cudaGetSymbolAddress(&pSlast, g_Slast);
  cudaGetSymbolAddress(&pBar,   g_barcnt);
  cudaGetSymbolAddress(&pHhi,   g_hhi);
  cudaGetSymbolAddress(&pHlo,   g_hlo);

  float* pool_dst = nullptr;
  float* cls_dst  = nullptr;
  if (out_size == B_*512 + B_*NC_)      { pool_dst = out; cls_dst = out + B_*512; }
  else if (out_size == B_*NC_)          { cls_dst = out; }
  else if (out_size == B_*512)          { pool_dst = out; }
  else { pool_dst = out; if (out_size >= B_*512 + B_*NC_) cls_dst = out + B_*512; }

  cudaFuncSetAttribute(k_mmagemm, cudaFuncAttributeMaxDynamicSharedMemorySize, 2*STG);
  cudaFuncSetAttribute(k_lstm_persist, cudaFuncAttributeMaxDynamicSharedMemorySize, L_SMEM);

  k_init_ahat<<<1, 32>>>();
  k_transpose<<<(GG*DD + 255)/256, 256>>>(Wih_f, (float*)pWihT, GG, DD);
  k_biasV<<<GG, 256>>>(Wih_f, bih_f, bhh_f, b2);
  k_split<<<(GG*DD/4 + 255)/256, 256>>>(Wih_b, (__nv_bfloat16*)pWbHi, (__nv_bfloat16*)pWbLo, GG*DD/4);

  // V fold: V_i = W2 @ WihT_f[i], then transpose+split -> Vt
  k_sgemm<<<dim3(8, 1, 17), 256>>>(128, GG, 128, W2, (const float*)pWihT, (float*)pV,
                                   nullptr, 0LL, (long long)128*GG, (long long)128*GG);
  k_tsplit<<<dim3(GG/32, DD/32), 256>>>((const float*)pV, (__nv_bfloat16*)pVtHi, (__nv_bfloat16*)pVtLo);

  // GCN layer 1 -> S split (+H10, Slast); E; split E
  k_layer1<<<T_*B_, 128>>>(pose1, pose2, W1, b1);
  k_E<<<T_, 128>>>();
  k_split<<<(T_*DD/4 + 255)/256, 256>>>((const float*)pE, (__nv_bfloat16*)pEhi, (__nv_bfloat16*)pElo, T_*DD/4);

  // pre = S @ V + biasV   (tensor-core split-bf16)
  k_mmagemm<<<dim3(8, 256), 256, 2*STG>>>((const __nv_bfloat16*)pShi, (const __nv_bfloat16*)pSlo,
                                          (const __nv_bfloat16*)pVtHi, (const __nv_bfloat16*)pVtLo,
                                          (float*)pPre, (const float*)pBias);
  // corr = E @ V ; pre[t, b=0, :] += corr[t]
  k_mmagemm<<<dim3(8, 2), 256, 2*STG>>>((const __nv_bfloat16*)pEhi, (const __nv_bfloat16*)pElo,
                                        (const __nv_bfloat16*)pVtHi, (const __nv_bfloat16*)pVtLo,
                                        (float*)pCorr, nullptr);
  k_addcorr<<<(T_*GG)/256, 256>>>();

  // backward: F = Slast @ W2 + b2; fix b=0; pre_b = F @ Wih_b^T
  k_sgemm<<<dim3(1, (B_*NN)/128, 1), 256>>>(B_*NN, 128, 128, (const float*)pSlast, W2,
                                            (float*)pF, b2, 0LL, 0LL, 0LL);
  k_fixF0<<<NN, 128>>>(W2);
  k_split<<<(B_*DD/4 + 255)/256, 256>>>((const float*)pF, (__nv_bfloat16*)pFhi, (__nv_bfloat16*)pFlo, B_*DD/4);
  k_mmagemm<<<dim3(8, 1), 256, 2*STG>>>((const __nv_bfloat16*)pFhi, (const __nv_bfloat16*)pFlo,
                                        (const __nv_bfloat16*)pWbHi, (const __nv_bfloat16*)pWbLo,
                                        (float*)pPreb, nullptr);

  // persistent forward LSTM (single kernel, grid-wide barrier per step)
  cudaMemsetAsync(pBar, 0, sizeof(unsigned));
  cudaMemsetAsync(pHhi, 0, (size_t)B_ * LH_ * sizeof(__nv_bfloat16));   // g_hhi[0]
  cudaMemsetAsync(pHlo, 0, (size_t)B_ * LH_ * sizeof(__nv_bfloat16));   // g_hlo[0]
  k_lstm_persist<<<LCTA, 256, L_SMEM>>>((const float*)pPre, Whh_f, (float*)pHA);

  k_backstep<<<B_, 256>>>(bih_b, bhh_b);
  k_pool<<<(B_*512)/256, 256>>>((const float*)pHA, pool_dst);
  if (cls_dst) k_cls<<<dim3(B_, 5), 128>>>(Wc, bc, cls_dst);
}

// round 16
// speedup vs baseline: 2.3354x; 1.0356x over previous
#include <cuda_runtime.h>
#include <cuda_bf16.h>
#include <math.h>
#include <stdint.h>

#define T_  256
#define B_  128
#define NN  17
#define DD  2176   // 17*128
#define GG  1024   // 4*256
#define LH_ 256
#define NC_ 625
#define LCTA 32    // persistent LSTM CTAs

__constant__ int c_conn[19][2] = {
  {15,13},{13,11},{16,14},{14,12},{11,12},{5,11},{6,12},{5,6},{5,7},{6,8},
  {7,9},{8,10},{1,2},{0,1},{0,2},{1,3},{2,4},{3,5},{4,6}
};

// ---- scratch (device globals) ----
__device__ float g_AHAT[NN*NN];
__device__ float g_AmI[NN*NN];
__device__ __nv_bfloat16 g_Shi[(size_t)T_*B_*DD];
__device__ __nv_bfloat16 g_Slo[(size_t)T_*B_*DD];
__device__ float g_Slast[(size_t)B_*DD];
__device__ float g_H10[(size_t)T_*NN*128];
__device__ float g_E[(size_t)T_*DD];
__device__ __nv_bfloat16 g_Ehi[(size_t)T_*DD];
__device__ __nv_bfloat16 g_Elo[(size_t)T_*DD];
__device__ float g_V[(size_t)DD*GG];
__device__ __nv_bfloat16 g_VtHi[(size_t)GG*DD];
__device__ __nv_bfloat16 g_VtLo[(size_t)GG*DD];
__device__ __nv_bfloat16 g_WbHi[(size_t)GG*DD];
__device__ __nv_bfloat16 g_WbLo[(size_t)GG*DD];
__device__ float g_WihT[(size_t)DD*GG];
__device__ float g_biasV[GG];
__device__ float g_pre[(size_t)T_*B_*GG];
__device__ float g_corr[(size_t)T_*GG];
__device__ float g_F[(size_t)B_*DD];
__device__ __nv_bfloat16 g_Fhi[(size_t)B_*DD];
__device__ __nv_bfloat16 g_Flo[(size_t)B_*DD];
__device__ float g_preb[(size_t)B_*GG];
__device__ float g_hA[B_*LH_];
__device__ float g_hbk[B_*LH_];
__device__ float g_pool[B_*512];
// persistent LSTM state
__device__ unsigned g_barcnt;
__device__ __nv_bfloat16 g_hhi[2][B_*LH_];
__device__ __nv_bfloat16 g_hlo[2][B_*LH_];

// ============================ helpers ============================
__device__ __forceinline__ uint32_t smem_u32(const void* p) {
  uint32_t a;
  asm("{ .reg .u64 t; cvta.to.shared.u64 t, %1; cvt.u32.u64 %0, t; }" : "=r"(a) : "l"(p));
  return a;
}
__device__ __forceinline__ void cp16(uint32_t saddr, const void* g) {
  asm volatile("cp.async.cg.shared.global [%0], [%1], 16;" :: "r"(saddr), "l"(g));
}
__device__ __forceinline__ void ldsm4(uint32_t addr, uint32_t& r0, uint32_t& r1,
                                      uint32_t& r2, uint32_t& r3) {
  asm volatile("ldmatrix.sync.aligned.m8n8.x4.shared.b16 {%0,%1,%2,%3}, [%4];"
               : "=r"(r0), "=r"(r1), "=r"(r2), "=r"(r3) : "r"(addr));
}
__device__ __forceinline__ void mma16816(float* c, const uint32_t* a, uint32_t b0, uint32_t b1) {
  asm volatile(
    "mma.sync.aligned.m16n8k16.row.col.f32.bf16.bf16.f32 "
    "{%0,%1,%2,%3}, {%4,%5,%6,%7}, {%8,%9}, {%0,%1,%2,%3};"
    : "+f"(c[0]), "+f"(c[1]), "+f"(c[2]), "+f"(c[3])
    : "r"(a[0]), "r"(a[1]), "r"(a[2]), "r"(a[3]), "r"(b0), "r"(b1));
}

// ============================ setup kernels ============================
__global__ void k_init_ahat() {
  if (threadIdx.x != 0 || blockIdx.x != 0) return;
  double deg[NN];
  for (int i = 0; i < NN; i++) deg[i] = 1.0;
  for (int e = 0; e < 19; e++) deg[c_conn[e][1]] += 1.0;
  double dis[NN];
  for (int i = 0; i < NN; i++) dis[i] = 1.0 / sqrt(deg[i]);
  double A[NN][NN];
  for (int i = 0; i < NN; i++) for (int j = 0; j < NN; j++) A[i][j] = 0.0;
  for (int e = 0; e < 19; e++) {
    int s = c_conn[e][0], d = c_conn[e][1];
    A[d][s] += dis[s] * dis[d];
  }
  for (int i = 0; i < NN; i++) A[i][i] += dis[i] * dis[i];
  for (int i = 0; i < NN; i++) for (int j = 0; j < NN; j++) {
    float v = (float)A[i][j];
    g_AHAT[i*NN+j] = v;
    g_AmI[i*NN+j]  = v - (i == j ? 1.f : 0.f);
  }
}

// coalesced tiled transpose: in [R][C] -> out [C][R]
__global__ void k_transpose(const float* __restrict__ in, float* __restrict__ out, int R, int C) {
  __shared__ float t[32][33];
  int bx = blockIdx.x;          // C/32
  int by = blockIdx.y;          // R/32
  int tx = threadIdx.x & 31, ty = threadIdx.x >> 5;
#pragma unroll
  for (int j = 0; j < 4; j++)
    t[ty + j*8][tx] = in[(size_t)(by*32 + ty + j*8) * C + bx*32 + tx];
  __syncthreads();
#pragma unroll
  for (int j = 0; j < 4; j++)
    out[(size_t)(bx*32 + ty + j*8) * R + by*32 + tx] = t[tx][ty + j*8];
}

__global__ void k_split(const float* __restrict__ in, __nv_bfloat16* __restrict__ hi,
                        __nv_bfloat16* __restrict__ lo, int n4) {
  int i = blockIdx.x * 256 + threadIdx.x;
  if (i >= n4) return;
  float4 v = ((const float4*)in)[i];
  __nv_bfloat16 hx = __float2bfloat16(v.x), hy = __float2bfloat16(v.y);
  __nv_bfloat16 hz = __float2bfloat16(v.z), hw = __float2bfloat16(v.w);
  __nv_bfloat16 lx = __float2bfloat16(v.x - __bfloat162float(hx));
  __nv_bfloat16 ly = __float2bfloat16(v.y - __bfloat162float(hy));
  __nv_bfloat16 lz = __float2bfloat16(v.z - __bfloat162float(hz));
  __nv_bfloat16 lw = __float2bfloat16(v.w - __bfloat162float(hw));
  __nv_bfloat162* H = (__nv_bfloat162*)hi;
  __nv_bfloat162* L = (__nv_bfloat162*)lo;
  H[2*i]   = __halves2bfloat162(hx, hy);
  H[2*i+1] = __halves2bfloat162(hz, hw);
  L[2*i]   = __halves2bfloat162(lx, ly);
  L[2*i+1] = __halves2bfloat162(lz, lw);
}

// transpose+split: in [DD][GG] fp32 -> out [GG][DD] bf16 hi/lo
__global__ void k_tsplit(const float* __restrict__ in, __nv_bfloat16* __restrict__ hi,
                         __nv_bfloat16* __restrict__ lo) {
  __shared__ float t[32][33];
  int bx = blockIdx.x;
  int by = blockIdx.y;
  int tx = threadIdx.x & 31, ty = threadIdx.x >> 5;
#pragma unroll
  for (int j = 0; j < 4; j++)
    t[ty + j*8][tx] = in[(size_t)(by*32 + ty + j*8) * GG + bx*32 + tx];
  __syncthreads();
#pragma unroll
  for (int j = 0; j < 4; j++) {
    float v = t[tx][ty + j*8];
    size_t o = (size_t)(bx*32 + ty + j*8) * DD + by*32 + tx;
    __nv_bfloat16 h = __float2bfloat16(v);
    hi[o] = h;
    lo[o] = __float2bfloat16(v - __bfloat162float(h));
  }
}

__global__ void k_biasV(const float* __restrict__ Wih, const float* __restrict__ bih,
                        const float* __restrict__ bhh, const float* __restrict__ b2) {
  int n = blockIdx.x;
  float acc = 0.f;
  const float* row = Wih + (size_t)n * DD;
  for (int ic = threadIdx.x; ic < DD; ic += 256) acc += b2[ic & 127] * row[ic];
  __shared__ float r[256];
  r[threadIdx.x] = acc;
  __syncthreads();
  for (int s = 128; s > 0; s >>= 1) {
    if (threadIdx.x < s) r[threadIdx.x] += r[threadIdx.x + s];
    __syncthreads();
  }
  if (threadIdx.x == 0) g_biasV[n] = r[0] + bih[n] + bhh[n];
}

// ---- generic SIMT SGEMM (small folds only) ----
__global__ void __launch_bounds__(256, 2)
k_sgemm(int M, int N, int K,
        const float* __restrict__ A, const float* __restrict__ B,
        float* __restrict__ C, const float* __restrict__ bias,
        long long sA, long long sB, long long sC) {
  A += (size_t)blockIdx.z * (size_t)sA;
  B += (size_t)blockIdx.z * (size_t)sB;
  C += (size_t)blockIdx.z * (size_t)sC;
  __shared__ float As[8][128];
  __shared__ float Bs[8][128];
  int tid = threadIdx.x;
  int m0 = blockIdx.y * 128, n0 = blockIdx.x * 128;
  int tx = tid & 15, ty = tid >> 4;
  int arow = tid >> 1, ak = (tid & 1) << 2;
  int bk = tid >> 5, bn = (tid & 31) << 2;
  float acc[8][8];
#pragma unroll
  for (int i = 0; i < 8; i++)
#pragma unroll
    for (int j = 0; j < 8; j++) acc[i][j] = 0.f;

  for (int k0 = 0; k0 < K; k0 += 8) {
    float4 av = make_float4(0.f, 0.f, 0.f, 0.f);
    if (m0 + arow < M) av = *(const float4*)(A + (size_t)(m0 + arow) * K + k0 + ak);
    float4 bv = make_float4(0.f, 0.f, 0.f, 0.f);
    if (n0 + bn < N) bv = *(const float4*)(B + (size_t)(k0 + bk) * N + n0 + bn);
    __syncthreads();
    As[ak+0][arow] = av.x; As[ak+1][arow] = av.y;
    As[ak+2][arow] = av.z; As[ak+3][arow] = av.w;
    *(float4*)&Bs[bk][bn] = bv;
    __syncthreads();
#pragma unroll
    for (int kk = 0; kk < 8; kk++) {
      float a[8], b[8];
      *(float4*)&a[0] = *(const float4*)&As[kk][ty*8];
      *(float4*)&a[4] = *(const float4*)&As[kk][ty*8+4];
      *(float4*)&b[0] = *(const float4*)&Bs[kk][tx*8];
      *(float4*)&b[4] = *(const float4*)&Bs[kk][tx*8+4];
#pragma unroll
      for (int i = 0; i < 8; i++)
#pragma unroll
        for (int j = 0; j < 8; j++) acc[i][j] += a[i] * b[j];
    }
  }
#pragma unroll
  for (int i = 0; i < 8; i++) {
    int m = m0 + ty*8 + i;
    if (m >= M) continue;
    float* cp = C + (size_t)m * N + n0 + tx*8;
#pragma unroll
    for (int j = 0; j < 8; j++) {
      float v = acc[i][j];
      if (bias) v += bias[n0 + tx*8 + j];
      cp[j] = v;
    }
  }
}

// ---- GCN layer 1 ----
__global__ void k_layer1(const float* __restrict__ pose1, const float* __restrict__ pose2,
                         const float* __restrict__ W1, const float* __restrict__ b1) {
  int bid = blockIdx.x;
  int c = threadIdx.x;
  int b = bid & 127, t = bid >> 7;
  __shared__ float sp1[NN*3], sp2[NN*3];
  __shared__ float sg[NN*128];
  size_t pbase = ((size_t)b * T_ + t) * NN * 3;
  if (c < NN*3) { sp1[c] = pose1[pbase + c]; sp2[c] = pose2[pbase + c]; }
  __syncthreads();
  float w0 = W1[c], w1 = W1[128 + c], w2 = W1[256 + c];
  float bb = b1[c];
  size_t srow = ((size_t)t * B_ + b) * NN;
  for (int i = 0; i < NN; i++) {
    float v1, v2;
    if (b == 0) {
      if (i == 0) {
        for (int ii = 0; ii < NN; ii++)
          sg[ii*128 + c] = sp1[ii*3]*w0 + sp1[ii*3+1]*w1 + sp1[ii*3+2]*w2;
        __syncthreads();
      }
      float agg = 0.f;
      for (int j = 0; j < NN; j++) agg += g_AHAT[i*NN+j] * sg[j*128 + c];
      v1 = fmaxf(agg + bb, 0.f);
      g_H10[((size_t)t*NN + i)*128 + c] = v1;
    } else {
      v1 = fmaxf(sp1[i*3]*w0 + sp1[i*3+1]*w1 + sp1[i*3+2]*w2 + bb, 0.f);
    }
    v2 = fmaxf(sp2[i*3]*w0 + sp2[i*3+1]*w1 + sp2[i*3+2]*w2 + bb, 0.f);
    float s = 0.5f * (v1 + v2);
    size_t o = (srow + i) * 128 + c;
    __nv_bfloat16 h = __float2bfloat16(s);
    g_Shi[o] = h;
    g_Slo[o] = __float2bfloat16(s - __bfloat162float(h));
    if (t == T_-1) g_Slast[((size_t)b*NN + i)*128 + c] = s;
  }
}

__global__ void k_E() {
  int t = blockIdx.x, c = threadIdx.x;
  __shared__ float sh[NN*128];
  for (int i = 0; i < NN; i++) sh[i*128 + c] = g_H10[((size_t)t*NN + i)*128 + c];
  __syncthreads();
  for (int i = 0; i < NN; i++) {
    float acc = 0.f;
    for (int j = 0; j < NN; j++) acc += g_AmI[i*NN+j] * sh[j*128 + c];
    g_E[((size_t)t*NN + i)*128 + c] = 0.5f * acc;
  }
}

__global__ void k_addcorr() {
  int idx = blockIdx.x * 256 + threadIdx.x;
  int t = idx >> 10, n = idx & 1023;
  g_pre[(size_t)t * B_ * GG + n] += g_corr[idx];
}

__global__ void k_fixF0(const float* __restrict__ W2) {
  int i = blockIdx.x, cc = threadIdx.x;
  __shared__ float se[128];
  se[cc] = g_E[((size_t)(T_-1)*NN + i)*128 + cc];
  __syncthreads();
  float acc = 0.f;
  for (int k = 0; k < 128; k++) acc += se[k] * W2[k*128 + cc];
  g_F[i*128 + cc] += acc;
}

// ============================ mma.sync split-bf16 GEMM (K-folded) ============================
// C = [Ahi|Ahi|Alo][M,3*2176] @ [Bhi|Blo|Bhi]^T : one bf16 GEMM, virtual K = 6528.
// stage = one A tile + one B tile (32KB); 3-stage cp.async pipeline; 2 CTAs/SM.
#define GSTG 32768

__device__ __forceinline__ void issue2(uint32_t dst, const __nv_bfloat16* A,
                                       const __nv_bfloat16* B, int m0, int n0,
                                       int cc, int tid) {
#pragma unroll
  for (int r = 0; r < 4; r++) {
    int idx = tid + r * 256;
    int row = idx >> 3, q = idx & 7;
    uint32_t off = (uint32_t)(row << 7) + (q << 4);
    off ^= (off >> 3) & 0x70;
    cp16(dst + off,         A + ((size_t)(m0 + row) * DD + cc * 64 + q * 8));
    cp16(dst + 16384 + off, B + ((size_t)(n0 + row) * DD + cc * 64 + q * 8));
  }
}

__global__ void __launch_bounds__(256, 2)
k_mmagemm(const __nv_bfloat16* __restrict__ Ahi, const __nv_bfloat16* __restrict__ Alo,
          const __nv_bfloat16* __restrict__ Bhi, const __nv_bfloat16* __restrict__ Blo,
          float* __restrict__ C, const float* __restrict__ bias) {
  extern __shared__ char sm[];
  uint32_t sb = smem_u32(sm);
  int tid = threadIdx.x, lane = tid & 31, w = tid >> 5;
  int wm = (w & 3) * 32;
  int wn = (w >> 2) * 64;
  int m0 = blockIdx.y << 7, n0 = blockIdx.x << 7;

  const __nv_bfloat16* Asrc[3] = {Ahi, Ahi, Alo};
  const __nv_bfloat16* Bsrc[3] = {Bhi, Blo, Bhi};

  float acc[2][8][4];
#pragma unroll
  for (int mt = 0; mt < 2; mt++)
#pragma unroll
    for (int nt = 0; nt < 8; nt++)
#pragma unroll
      for (int j = 0; j < 4; j++) acc[mt][nt][j] = 0.f;

  const int NCH = 102;    // 3 * 34
  issue2(sb + 0*GSTG, Asrc[0], Bsrc[0], m0, n0, 0, tid);
  asm volatile("cp.async.commit_group;");
  issue2(sb + 1*GSTG, Asrc[0], Bsrc[0], m0, n0, 1, tid);
  asm volatile("cp.async.commit_group;");
  issue2(sb + 2*GSTG, Asrc[0], Bsrc[0], m0, n0, 2, tid);
  asm volatile("cp.async.commit_group;");

  int stg = 0;
#pragma unroll 1
  for (int ch = 0; ch < NCH; ch++) {
    if (ch < NCH - 2)      asm volatile("cp.async.wait_group 2;");
    else if (ch == NCH - 2) asm volatile("cp.async.wait_group 1;");
    else                    asm volatile("cp.async.wait_group 0;");
    __syncthreads();
    uint32_t cur = sb + (uint32_t)stg * GSTG;

#pragma unroll
    for (int ks = 0; ks < 4; ks++) {
      uint32_t ah[2][4];
#pragma unroll
      for (int mt = 0; mt < 2; mt++) {
        uint32_t row = wm + mt * 16 + (lane & 15);
        uint32_t off = (row << 7) + ks * 32 + ((lane >> 4) << 4);
        off ^= (off >> 3) & 0x70;
        ldsm4(cur + off, ah[mt][0], ah[mt][1], ah[mt][2], ah[mt][3]);
      }
      uint32_t bh[4][4];
#pragma unroll
      for (int ng = 0; ng < 4; ng++) {
        uint32_t row = wn + ng * 16 + (lane & 15);
        uint32_t off = (row << 7) + ks * 32 + ((lane >> 4) << 4);
        off ^= (off >> 3) & 0x70;
        ldsm4(cur + 16384 + off, bh[ng][0], bh[ng][1], bh[ng][2], bh[ng][3]);
      }
#pragma unroll
      for (int mt = 0; mt < 2; mt++)
#pragma unroll
        for (int ng = 0; ng < 4; ng++) {
          mma16816(acc[mt][ng*2],   ah[mt], bh[ng][0], bh[ng][2]);
          mma16816(acc[mt][ng*2+1], ah[mt], bh[ng][1], bh[ng][3]);
        }
    }
    __syncthreads();
    int nx = ch + 3;
    if (nx < NCH) {
      int s = (nx >= 68) ? 2 : ((nx >= 34) ? 1 : 0);
      issue2(cur, Asrc[s], Bsrc[s], m0, n0, nx - s * 34, tid);
      asm volatile("cp.async.commit_group;");
    }
    stg = (stg + 1 == 3) ? 0 : stg + 1;
  }

#pragma unroll
  for (int mt = 0; mt < 2; mt++) {
    int r = m0 + wm + mt * 16 + (lane >> 2);
#pragma unroll
    for (int nt = 0; nt < 8; nt++) {
      int cc = n0 + wn + nt * 8 + (lane & 3) * 2;
      float b0 = 0.f, b1 = 0.f;
      if (bias) { b0 = bias[cc]; b1 = bias[cc + 1]; }
      float2 v0 = make_float2(acc[mt][nt][0] + b0, acc[mt][nt][1] + b1);
      float2 v1 = make_float2(acc[mt][nt][2] + b0, acc[mt][nt][3] + b1);
      *(float2*)(C + (size_t)r * GG + cc) = v0;
      *(float2*)(C + (size_t)(r + 8) * GG + cc) = v1;
    }
  }
}

// ============================ persistent fused forward LSTM ============================
#define L_OBHI 0
#define L_OBLO 16384
#define L_OAHI 32768
#define L_OALO 98304
#define L_SMEM 163840

__device__ __forceinline__ float sigf(float x) { return 1.f / (1.f + expf(-x)); }

__global__ void __launch_bounds__(256, 1)
k_lstm_persist(const float* __restrict__ pre, const float* __restrict__ Whh,
               float* __restrict__ hfin) {
  extern __shared__ char sm[];
  uint32_t sb = smem_u32(sm);
  int tid = threadIdx.x, lane = tid & 31, w = tid >> 5;
  int jb = blockIdx.x;

  // preload Whh slice: smem row (g*8+jj) <- global row g*256 + jb*8 + jj; split+swizzle
  for (int idx = tid; idx < 32 * 32; idx += 256) {
    int row = idx >> 5, q32 = idx & 31;
    int kc = q32 >> 3, q = q32 & 7;
    int g = row >> 3, jj = row & 7;
    const float* src = Whh + (size_t)(g * 256 + jb * 8 + jj) * LH_ + q32 * 8;
    float vv[8];
    *(float4*)&vv[0] = *(const float4*)src;
    *(float4*)&vv[4] = *(const float4*)(src + 4);
    __nv_bfloat16 h8[8], l8[8];
#pragma unroll
    for (int e = 0; e < 8; e++) {
      h8[e] = __float2bfloat16(vv[e]);
      l8[e] = __float2bfloat16(vv[e] - __bfloat162float(h8[e]));
    }
    uint32_t off = (uint32_t)(row << 7) + (q << 4);
    off ^= (off >> 3) & 0x70;
    *(float4*)(sm + L_OBHI + kc * 4096 + off) = *(float4*)h8;
    *(float4*)(sm + L_OBLO + kc * 4096 + off) = *(float4*)l8;
  }
  float c4[4] = {0.f, 0.f, 0.f, 0.f};
  __syncthreads();

  int r0 = w * 16 + (lane >> 2);
  int j  = jb * 8 + (lane & 3) * 2;

#pragma unroll 1
  for (int t = 0; t < T_; t++) {
    // prefetch pre[t] contributions into registers BEFORE the grid barrier
    const float* pb = pre + (size_t)t * B_ * GG;
    float prv[4][4];
#pragma unroll
    for (int e = 0; e < 4; e++) {
      int b = r0 + (e >> 1) * 8;
      int jc = j + (e & 1);
      const float* pr = pb + (size_t)b * GG + jc;
      prv[0][e] = pr[0];
      prv[1][e] = pr[256];
      prv[2][e] = pr[512];
      prv[3][e] = pr[768];
    }

    if (t > 0) {
      if (tid == 0) {
        volatile unsigned* p = &g_barcnt;
        while (*p < (unsigned)(LCTA * t)) { }
      }
      __syncthreads();
      __threadfence();
    }
    const __nv_bfloat16* Hh = g_hhi[t & 1];
    const __nv_bfloat16* Hl = g_hlo[t & 1];
#pragma unroll
    for (int r = 0; r < 16; r++) {
      int idx = tid + r * 256;
      int row = idx >> 5, q32 = idx & 31;
      int kc = q32 >> 3, q = q32 & 7;
      uint32_t off = (uint32_t)(row << 7) + (q << 4);
      off ^= (off >> 3) & 0x70;
      cp16(sb + L_OAHI + kc * 16384 + off, Hh + row * LH_ + q32 * 8);
      cp16(sb + L_OALO + kc * 16384 + off, Hl + row * LH_ + q32 * 8);
    }
    asm volatile("cp.async.commit_group;");
    asm volatile("cp.async.wait_group 0;");
    __syncthreads();

    float acc[4][4];
#pragma unroll
    for (int g = 0; g < 4; g++)
#pragma unroll
      for (int e = 0; e < 4; e++) acc[g][e] = 0.f;

#pragma unroll 1
    for (int kc = 0; kc < 4; kc++) {
      uint32_t abase  = sb + L_OAHI + kc * 16384;
      uint32_t abase2 = sb + L_OALO + kc * 16384;
      uint32_t bbase  = sb + L_OBHI + kc * 4096;
      uint32_t bbase2 = sb + L_OBLO + kc * 4096;
#pragma unroll
      for (int ks = 0; ks < 4; ks++) {
        uint32_t ah[4], al[4];
        {
          uint32_t row = w * 16 + (lane & 15);
          uint32_t off = (row << 7) + ks * 32 + ((lane >> 4) << 4);
          off ^= (off >> 3) & 0x70;
          ldsm4(abase + off, ah[0], ah[1], ah[2], ah[3]);
          ldsm4(abase2 + off, al[0], al[1], al[2], al[3]);
        }
        uint32_t bh[2][4], bl[2][4];
#pragma unroll
        for (int ng = 0; ng < 2; ng++) {
          uint32_t row = ng * 16 + (lane & 15);
          uint32_t off = (row << 7) + ks * 32 + ((lane >> 4) << 4);
          off ^= (off >> 3) & 0x70;
          ldsm4(bbase + off, bh[ng][0], bh[ng][1], bh[ng][2], bh[ng][3]);
          ldsm4(bbase2 + off, bl[ng][0], bl[ng][1], bl[ng][2], bl[ng][3]);
        }
#pragma unroll
        for (int ng = 0; ng < 2; ng++) {
          mma16816(acc[ng*2],   ah, bh[ng][0], bh[ng][2]);
          mma16816(acc[ng*2+1], ah, bh[ng][1], bh[ng][3]);
          mma16816(acc[ng*2],   ah, bl[ng][0], bl[ng][2]);
          mma16816(acc[ng*2+1], ah, bl[ng][1], bl[ng][3]);
          mma16816(acc[ng*2],   al, bh[ng][0], bh[ng][2]);
          mma16816(acc[ng*2+1], al, bh[ng][1], bh[ng][3]);
        }
      }
    }

    __nv_bfloat16* Whi = g_hhi[(t + 1) & 1];
    __nv_bfloat16* Wlo = g_hlo[(t + 1) & 1];
#pragma unroll
    for (int e = 0; e < 4; e++) {
      int b = r0 + (e >> 1) * 8;
      int jc = j + (e & 1);
      float zi = acc[0][e] + prv[0][e];
      float zf = acc[1][e] + prv[1][e];
      float zg = acc[2][e] + prv[2][e];
      float zo = acc[3][e] + prv[3][e];
      float cn = sigf(zf) * c4[e] + sigf(zi) * tanhf(zg);
      c4[e] = cn;
      float hv = sigf(zo) * tanhf(cn);
      __nv_bfloat16 hh = __float2bfloat16(hv);
      Whi[b * LH_ + jc] = hh;
      Wlo[b * LH_ + jc] = __float2bfloat16(hv - __bfloat162float(hh));
      if (t == T_ - 1) hfin[b * LH_ + jc] = hv;
    }
    __threadfence();
    __syncthreads();
    if (tid == 0) atomicAdd(&g_barcnt, 1u);
  }
}

// ============================ tail kernels ============================
__global__ void k_backstep(const float* __restrict__ bih, const float* __restrict__ bhh) {
  int b = blockIdx.x, jx = threadIdx.x;
  const float* pr = g_preb + (size_t)b * GG;
  float zi = pr[jx]       + bih[jx]       + bhh[jx];
  float zg = pr[512 + jx] + bih[512 + jx] + bhh[512 + jx];
  float zo = pr[768 + jx] + bih[768 + jx] + bhh[768 + jx];
  float cn = sigf(zi) * tanhf(zg);
  g_hbk[b * LH_ + jx] = sigf(zo) * tanhf(cn);
}

__global__ void k_pool(const float* __restrict__ hf, float* outp) {
  int idx = blockIdx.x * 256 + threadIdx.x;
  int b = idx >> 9, d = idx & 511;
  float v = (d < 256) ? hf[b * 256 + d] : g_hbk[b * 256 + d - 256];
  v = fmaxf(v, 0.f);
  g_pool[idx] = v;
  if (outp) outp[idx] = v;
}

__global__ void k_cls(const float* __restrict__ Wc, const float* __restrict__ bc,
                      float* __restrict__ outc) {
  int b = blockIdx.x;
  int m = blockIdx.y * 128 + threadIdx.x;
  __shared__ float sp[512];
  int t = threadIdx.x;
  sp[t] = g_pool[b*512 + t]; sp[t+128] = g_pool[b*512 + t + 128];
  sp[t+256] = g_pool[b*512 + t + 256]; sp[t+384] = g_pool[b*512 + t + 384];
  __syncthreads();
  if (m < NC_) {
    float acc = bc[m];
    const float* wr = Wc + (size_t)m * 512;
    for (int d = 0; d < 512; d++) acc += sp[d] * wr[d];
    outc[(size_t)b * NC_ + m] = acc;
  }
}

// ============================ host ============================
extern "C" void kernel_launch(void* const* d_in, const int* in_sizes, int n_in,
                              void* d_out, int out_size) {
  const float* pose1 = (const float*)d_in[0];
  const float* pose2 = (const float*)d_in[1];
  const float* W1    = (const float*)d_in[2];
  const float* b1    = (const float*)d_in[3];
  const float* W2    = (const float*)d_in[4];
  const float* b2    = (const float*)d_in[5];
  const float* Wih_f = (const float*)d_in[6];
  const float* Whh_f = (const float*)d_in[7];
  const float* bih_f = (const float*)d_in[8];
  const float* bhh_f = (const float*)d_in[9];
  const float* Wih_b = (const float*)d_in[10];
  const float* Whh_b = (const float*)d_in[11];
  const float* bih_b = (const float*)d_in[12];
  const float* bhh_b = (const float*)d_in[13];
  const float* Wc    = (const float*)d_in[14];
  const float* bc    = (const float*)d_in[15];
  (void)Whh_b; (void)in_sizes; (void)n_in;
  float* out = (float*)d_out;

  void *pWihT, *pV, *pPre, *pE, *pF, *pPreb, *pBias, *pHA;
  void *pShi, *pSlo, *pVtHi, *pVtLo, *pWbHi, *pWbLo, *pEhi, *pElo, *pFhi, *pFlo, *pCorr, *pSlast;
  void *pBar, *pHhi, *pHlo;
  cudaGetSymbolAddress(&pWihT,  g_WihT);
  cudaGetSymbolAddress(&pV,     g_V);
  cudaGetSymbolAddress(&pPre,   g_pre);
  cudaGetSymbolAddress(&pE,     g_E);
  cudaGetSymbolAddress(&pF,     g_F);
  cudaGetSymbolAddress(&pPreb,  g_preb);
  cudaGetSymbolAddress(&pBias,  g_biasV);
  cudaGetSymbolAddress(&pHA,    g_hA);
  cudaGetSymbolAddress(&pShi,   g_Shi);
  cudaGetSymbolAddress(&pSlo,   g_Slo);
  cudaGetSymbolAddress(&pVtHi,  g_VtHi);
  cudaGetSymbolAddress(&pVtLo,  g_VtLo);
  cudaGetSymbolAddress(&pWbHi,  g_WbHi);
  cudaGetSymbolAddress(&pWbLo,  g_WbLo);
  cudaGetSymbolAddress(&pEhi,   g_Ehi);
  cudaGetSymbolAddress(&pElo,   g_Elo);
  cudaGetSymbolAddress(&pFhi,   g_Fhi);
  cudaGetSymbolAddress(&pFlo,   g_Flo);
  cudaGetSymbolAddress(&pCorr,  g_corr);
  cudaGetSymbolAddress(&pSlast, g_Slast);
  cudaGetSymbolAddress(&pBar,   g_barcnt);
  cudaGetSymbolAddress(&pHhi,   g_hhi);
  cudaGetSymbolAddress(&pHlo,   g_hlo);

  float* pool_dst = nullptr;
  float* cls_dst  = nullptr;
  if (out_size == B_*512 + B_*NC_)      { pool_dst = out; cls_dst = out + B_*512; }
  else if (out_size == B_*NC_)          { cls_dst = out; }
  else if (out_size == B_*512)          { pool_dst = out; }
  else { pool_dst = out; if (out_size >= B_*512 + B_*NC_) cls_dst = out + B_*512; }

  cudaFuncSetAttribute(k_mmagemm, cudaFuncAttributeMaxDynamicSharedMemorySize, 3*GSTG);
  cudaFuncSetAttribute(k_lstm_persist, cudaFuncAttributeMaxDynamicSharedMemorySize, L_SMEM);

  k_init_ahat<<<1, 32>>>();
  k_transpose<<<dim3(DD/32, GG/32), 256>>>(Wih_f, (float*)pWihT, GG, DD);
  k_biasV<<<GG, 256>>>(Wih_f, bih_f, bhh_f, b2);
  k_split<<<(GG*DD/4 + 255)/256, 256>>>(Wih_b, (__nv_bfloat16*)pWbHi, (__nv_bfloat16*)pWbLo, GG*DD/4);

  // V fold: V_i = W2 @ WihT_f[i], then transpose+split -> Vt
  k_sgemm<<<dim3(8, 1, 17), 256>>>(128, GG, 128, W2, (const float*)pWihT, (float*)pV,
                                   nullptr, 0LL, (long long)128*GG, (long long)128*GG);
  k_tsplit<<<dim3(GG/32, DD/32), 256>>>((const float*)pV, (__nv_bfloat16*)pVtHi, (__nv_bfloat16*)pVtLo);

  // GCN layer 1 -> S split (+H10, Slast); E; split E
  k_layer1<<<T_*B_, 128>>>(pose1, pose2, W1, b1);
  k_E<<<T_, 128>>>();
  k_split<<<(T_*DD/4 + 255)/256, 256>>>((const float*)pE, (__nv_bfloat16*)pEhi, (__nv_bfloat16*)pElo, T_*DD/4);

  // pre = S @ V + biasV   (K-folded split-bf16 tensor GEMM)
  k_mmagemm<<<dim3(8, 256), 256, 3*GSTG>>>((const __nv_bfloat16*)pShi, (const __nv_bfloat16*)pSlo,
                                           (const __nv_bfloat16*)pVtHi, (const __nv_bfloat16*)pVtLo,
                                           (float*)pPre, (const float*)pBias);
  // corr = E @ V ; pre[t, b=0, :] += corr[t]
  k_mmagemm<<<dim3(8, 2), 256, 3*GSTG>>>((const __nv_bfloat16*)pEhi, (const __nv_bfloat16*)pElo,
                                         (const __nv_bfloat16*)pVtHi, (const __nv_bfloat16*)pVtLo,
                                         (float*)pCorr, nullptr);
  k_addcorr<<<(T_*GG)/256, 256>>>();

  // backward: F = Slast @ W2 + b2; fix b=0; pre_b = F @ Wih_b^T
  k_sgemm<<<dim3(1, (B_*NN)/128, 1), 256>>>(B_*NN, 128, 128, (const float*)pSlast, W2,
                                            (float*)pF, b2, 0LL, 0LL, 0LL);
  k_fixF0<<<NN, 128>>>(W2);
  k_split<<<(B_*DD/4 + 255)/256, 256>>>((const float*)pF, (__nv_bfloat16*)pFhi, (__nv_bfloat16*)pFlo, B_*DD/4);
  k_mmagemm<<<dim3(8, 1), 256, 3*GSTG>>>((const __nv_bfloat16*)pFhi, (const __nv_bfloat16*)pFlo,
                                         (const __nv_bfloat16*)pWbHi, (const __nv_bfloat16*)pWbLo,
                                         (float*)pPreb, nullptr);

  // persistent forward LSTM (single kernel, grid-wide barrier per step)
  cudaMemsetAsync(pBar, 0, sizeof(unsigned));
  cudaMemsetAsync(pHhi, 0, (size_t)B_ * LH_ * sizeof(__nv_bfloat16));   // g_hhi[0]
  cudaMemsetAsync(pHlo, 0, (size_t)B_ * LH_ * sizeof(__nv_bfloat16));   // g_hlo[0]
  k_lstm_persist<<<LCTA, 256, L_SMEM>>>((const float*)pPre, Whh_f, (float*)pHA);

  k_backstep<<<B_, 256>>>(bih_b, bhh_b);
  k_pool<<<(B_*512)/256, 256>>>((const float*)pHA, pool_dst);
  if (cls_dst) k_cls<<<dim3(B_, 5), 128>>>(Wc, bc, cls_dst);
}

// round 17
// speedup vs baseline: 2.4458x; 1.0473x over previous
#include <cuda_runtime.h>
#include <cuda_bf16.h>
#include <math.h>
#include <stdint.h>

#define T_  256
#define B_  128
#define NN  17
#define DD  2176   // 17*128
#define GG  1024   // 4*256
#define LH_ 256
#define NC_ 625
#define LCTA 32    // persistent LSTM CTAs
#define MR  (T_*B_ + T_)   // GEMM A rows: S rows + appended E rows (33024)

__constant__ int c_conn[19][2] = {
  {15,13},{13,11},{16,14},{14,12},{11,12},{5,11},{6,12},{5,6},{5,7},{6,8},
  {7,9},{8,10},{1,2},{0,1},{0,2},{1,3},{2,4},{3,5},{4,6}
};

// ---- scratch (device globals) ----
__device__ __nv_bfloat16 g_Shi[(size_t)MR*DD];   // S rows + E-correction tail rows
__device__ __nv_bfloat16 g_Slo[(size_t)MR*DD];
__device__ float g_Slast[(size_t)B_*DD];
__device__ float g_E[NN*128];                    // fp32 E at t = T-1 only (for fixF0)
__device__ __nv_bfloat16 g_VtHi[(size_t)GG*DD];
__device__ __nv_bfloat16 g_VtLo[(size_t)GG*DD];
__device__ __nv_bfloat16 g_WbHi[(size_t)GG*DD];
__device__ __nv_bfloat16 g_WbLo[(size_t)GG*DD];
__device__ float g_biasV[GG];
__device__ float g_pre[(size_t)MR*GG];           // pre rows + corr tail rows
__device__ float g_F[(size_t)B_*DD];
__device__ __nv_bfloat16 g_Fhi[(size_t)B_*DD];
__device__ __nv_bfloat16 g_Flo[(size_t)B_*DD];
__device__ float g_preb[(size_t)B_*GG];
__device__ float g_hA[B_*LH_];
__device__ float g_hbk[B_*LH_];
__device__ float g_pool[B_*512];
// persistent LSTM state
__device__ unsigned g_barcnt;
__device__ __nv_bfloat16 g_hhi[2][B_*LH_];
__device__ __nv_bfloat16 g_hlo[2][B_*LH_];

// ============================ helpers ============================
__device__ __forceinline__ uint32_t smem_u32(const void* p) {
  uint32_t a;
  asm("{ .reg .u64 t; cvta.to.shared.u64 t, %1; cvt.u32.u64 %0, t; }" : "=r"(a) : "l"(p));
  return a;
}
__device__ __forceinline__ void cp16(uint32_t saddr, const void* g) {
  asm volatile("cp.async.cg.shared.global [%0], [%1], 16;" :: "r"(saddr), "l"(g));
}
__device__ __forceinline__ void ldsm4(uint32_t addr, uint32_t& r0, uint32_t& r1,
                                      uint32_t& r2, uint32_t& r3) {
  asm volatile("ldmatrix.sync.aligned.m8n8.x4.shared.b16 {%0,%1,%2,%3}, [%4];"
               : "=r"(r0), "=r"(r1), "=r"(r2), "=r"(r3) : "r"(addr));
}
__device__ __forceinline__ void mma16816(float* c, const uint32_t* a, uint32_t b0, uint32_t b1) {
  asm volatile(
    "mma.sync.aligned.m16n8k16.row.col.f32.bf16.bf16.f32 "
    "{%0,%1,%2,%3}, {%4,%5,%6,%7}, {%8,%9}, {%0,%1,%2,%3};"
    : "+f"(c[0]), "+f"(c[1]), "+f"(c[2]), "+f"(c[3])
    : "r"(a[0]), "r"(a[1]), "r"(a[2]), "r"(a[3]), "r"(b0), "r"(b1));
}

// ============================ V fold (direct) ============================
// Vt[n, z*128 + c] = sum_m Wih[n, z*128+m] * W2[c][m]  (B read transposed),
// emitted as split bf16 hi/lo. Grid (1, 8, 17).
__global__ void __launch_bounds__(256, 2)
k_vfold(const float* __restrict__ Wih, const float* __restrict__ W2,
        __nv_bfloat16* __restrict__ hi, __nv_bfloat16* __restrict__ lo) {
  int z = blockIdx.z;
  const float* A = Wih + z * 128;     // row stride DD
  __shared__ float As[8][128];
  __shared__ float Bs[8][128];
  int tid = threadIdx.x;
  int m0 = blockIdx.y * 128;
  int tx = tid & 15, ty = tid >> 4;
  int arow = tid >> 1, ak = (tid & 1) << 2;
  int bk = tid >> 5, bn = (tid & 31) << 2;
  float acc[8][8];
#pragma unroll
  for (int i = 0; i < 8; i++)
#pragma unroll
    for (int j = 0; j < 8; j++) acc[i][j] = 0.f;

  for (int k0 = 0; k0 < 128; k0 += 8) {
    float4 av = *(const float4*)(A + (size_t)(m0 + arow) * DD + k0 + ak);
    float b0 = W2[(bn + 0) * 128 + k0 + bk];
    float b1 = W2[(bn + 1) * 128 + k0 + bk];
    float b2v = W2[(bn + 2) * 128 + k0 + bk];
    float b3 = W2[(bn + 3) * 128 + k0 + bk];
    __syncthreads();
    As[ak+0][arow] = av.x; As[ak+1][arow] = av.y;
    As[ak+2][arow] = av.z; As[ak+3][arow] = av.w;
    Bs[bk][bn+0] = b0; Bs[bk][bn+1] = b1; Bs[bk][bn+2] = b2v; Bs[bk][bn+3] = b3;
    __syncthreads();
#pragma unroll
    for (int kk = 0; kk < 8; kk++) {
      float a[8], b[8];
      *(float4*)&a[0] = *(const float4*)&As[kk][ty*8];
      *(float4*)&a[4] = *(const float4*)&As[kk][ty*8+4];
      *(float4*)&b[0] = *(const float4*)&Bs[kk][tx*8];
      *(float4*)&b[4] = *(const float4*)&Bs[kk][tx*8+4];
#pragma unroll
      for (int i = 0; i < 8; i++)
#pragma unroll
        for (int j = 0; j < 8; j++) acc[i][j] += a[i] * b[j];
    }
  }
#pragma unroll
  for (int i = 0; i < 8; i++) {
    size_t base = (size_t)(m0 + ty*8 + i) * DD + z * 128 + tx * 8;
#pragma unroll
    for (int j = 0; j < 8; j++) {
      float v = acc[i][j];
      __nv_bfloat16 h = __float2bfloat16(v);
      hi[base + j] = h;
      lo[base + j] = __float2bfloat16(v - __bfloat162float(h));
    }
  }
}

__global__ void k_split(const float* __restrict__ in, __nv_bfloat16* __restrict__ hi,
                        __nv_bfloat16* __restrict__ lo, int n4) {
  int i = blockIdx.x * 256 + threadIdx.x;
  if (i >= n4) return;
  float4 v = ((const float4*)in)[i];
  __nv_bfloat16 hx = __float2bfloat16(v.x), hy = __float2bfloat16(v.y);
  __nv_bfloat16 hz = __float2bfloat16(v.z), hw = __float2bfloat16(v.w);
  __nv_bfloat16 lx = __float2bfloat16(v.x - __bfloat162float(hx));
  __nv_bfloat16 ly = __float2bfloat16(v.y - __bfloat162float(hy));
  __nv_bfloat16 lz = __float2bfloat16(v.z - __bfloat162float(hz));
  __nv_bfloat16 lw = __float2bfloat16(v.w - __bfloat162float(hw));
  __nv_bfloat162* H = (__nv_bfloat162*)hi;
  __nv_bfloat162* L = (__nv_bfloat162*)lo;
  H[2*i]   = __halves2bfloat162(hx, hy);
  H[2*i+1] = __halves2bfloat162(hz, hw);
  L[2*i]   = __halves2bfloat162(lx, ly);
  L[2*i+1] = __halves2bfloat162(lz, lw);
}

__global__ void k_biasV(const float* __restrict__ Wih, const float* __restrict__ bih,
                        const float* __restrict__ bhh, const float* __restrict__ b2) {
  int n = blockIdx.x;
  float acc = 0.f;
  const float* row = Wih + (size_t)n * DD;
  for (int ic = threadIdx.x; ic < DD; ic += 256) acc += b2[ic & 127] * row[ic];
  __shared__ float r[256];
  r[threadIdx.x] = acc;
  __syncthreads();
  for (int s = 128; s > 0; s >>= 1) {
    if (threadIdx.x < s) r[threadIdx.x] += r[threadIdx.x + s];
    __syncthreads();
  }
  if (threadIdx.x == 0) g_biasV[n] = r[0] + bih[n] + bhh[n];
}

// ---- generic SIMT SGEMM (small folds only) ----
__global__ void __launch_bounds__(256, 2)
k_sgemm(int M, int N, int K,
        const float* __restrict__ A, const float* __restrict__ B,
        float* __restrict__ C, const float* __restrict__ bias,
        long long sA, long long sB, long long sC) {
  A += (size_t)blockIdx.z * (size_t)sA;
  B += (size_t)blockIdx.z * (size_t)sB;
  C += (size_t)blockIdx.z * (size_t)sC;
  __shared__ float As[8][128];
  __shared__ float Bs[8][128];
  int tid = threadIdx.x;
  int m0 = blockIdx.y * 128, n0 = blockIdx.x * 128;
  int tx = tid & 15, ty = tid >> 4;
  int arow = tid >> 1, ak = (tid & 1) << 2;
  int bk = tid >> 5, bn = (tid & 31) << 2;
  float acc[8][8];
#pragma unroll
  for (int i = 0; i < 8; i++)
#pragma unroll
    for (int j = 0; j < 8; j++) acc[i][j] = 0.f;

  for (int k0 = 0; k0 < K; k0 += 8) {
    float4 av = make_float4(0.f, 0.f, 0.f, 0.f);
    if (m0 + arow < M) av = *(const float4*)(A + (size_t)(m0 + arow) * K + k0 + ak);
    float4 bv = make_float4(0.f, 0.f, 0.f, 0.f);
    if (n0 + bn < N) bv = *(const float4*)(B + (size_t)(k0 + bk) * N + n0 + bn);
    __syncthreads();
    As[ak+0][arow] = av.x; As[ak+1][arow] = av.y;
    As[ak+2][arow] = av.z; As[ak+3][arow] = av.w;
    *(float4*)&Bs[bk][bn] = bv;
    __syncthreads();
#pragma unroll
    for (int kk = 0; kk < 8; kk++) {
      float a[8], b[8];
      *(float4*)&a[0] = *(const float4*)&As[kk][ty*8];
      *(float4*)&a[4] = *(const float4*)&As[kk][ty*8+4];
      *(float4*)&b[0] = *(const float4*)&Bs[kk][tx*8];
      *(float4*)&b[4] = *(const float4*)&Bs[kk][tx*8+4];
#pragma unroll
      for (int i = 0; i < 8; i++)
#pragma unroll
        for (int j = 0; j < 8; j++) acc[i][j] += a[i] * b[j];
    }
  }
#pragma unroll
  for (int i = 0; i < 8; i++) {
    int m = m0 + ty*8 + i;
    if (m >= M) continue;
    float* cp = C + (size_t)m * N + n0 + tx*8;
#pragma unroll
    for (int j = 0; j < 8; j++) {
      float v = acc[i][j];
      if (bias) v += bias[n0 + tx*8 + j];
      cp[j] = v;
    }
  }
}

// ---- GCN layer 1 (adjacency inline; also emits E-correction tail rows) ----
__global__ void k_layer1(const float* __restrict__ pose1, const float* __restrict__ pose2,
                         const float* __restrict__ W1, const float* __restrict__ b1) {
  int bid = blockIdx.x;
  int c = threadIdx.x;
  int b = bid & 127, t = bid >> 7;
  __shared__ float sp1[NN*3], sp2[NN*3];
  __shared__ float sg[NN*128];
  __shared__ float sv[NN*128];
  __shared__ float sA[NN*NN];
  size_t pbase = ((size_t)b * T_ + t) * NN * 3;
  if (c < NN*3) { sp1[c] = pose1[pbase + c]; sp2[c] = pose2[pbase + c]; }
  if (b == 0 && c == 0) {
    // PyG GCNConv norm in f64 (matches reference)
    double deg[NN];
    for (int i = 0; i < NN; i++) deg[i] = 1.0;
    for (int e = 0; e < 19; e++) deg[c_conn[e][1]] += 1.0;
    double dis[NN];
    for (int i = 0; i < NN; i++) dis[i] = 1.0 / sqrt(deg[i]);
    for (int i = 0; i < NN*NN; i++) sA[i] = 0.f;
    for (int e = 0; e < 19; e++) {
      int s = c_conn[e][0], d = c_conn[e][1];
      sA[d*NN + s] += (float)(dis[s] * dis[d]);
    }
    for (int i = 0; i < NN; i++) sA[i*NN + i] += (float)(dis[i] * dis[i]);
  }
  __syncthreads();
  float w0 = W1[c], w1 = W1[128 + c], w2 = W1[256 + c];
  float bb = b1[c];
  size_t srow = ((size_t)t * B_ + b) * NN;
  for (int i = 0; i < NN; i++) {
    float v1, v2;
    if (b == 0) {
      if (i == 0) {
        for (int ii = 0; ii < NN; ii++)
          sg[ii*128 + c] = sp1[ii*3]*w0 + sp1[ii*3+1]*w1 + sp1[ii*3+2]*w2;
        __syncthreads();
      }
      float agg = 0.f;
      for (int j = 0; j < NN; j++) agg += sA[i*NN+j] * sg[j*128 + c];
      v1 = fmaxf(agg + bb, 0.f);
      sv[i*128 + c] = v1;
    } else {
      v1 = fmaxf(sp1[i*3]*w0 + sp1[i*3+1]*w1 + sp1[i*3+2]*w2 + bb, 0.f);
    }
    v2 = fmaxf(sp2[i*3]*w0 + sp2[i*3+1]*w1 + sp2[i*3+2]*w2 + bb, 0.f);
    float s = 0.5f * (v1 + v2);
    size_t o = (srow + i) * 128 + c;
    __nv_bfloat16 h = __float2bfloat16(s);
    g_Shi[o] = h;
    g_Slo[o] = __float2bfloat16(s - __bfloat162float(h));
    if (t == T_-1) g_Slast[((size_t)b*NN + i)*128 + c] = s;
  }
  if (b == 0) {
    // E[t] = 0.5*(A - I) @ H10[t]  -> tail rows of the GEMM A matrix
    // (sv column c is written and read by the same thread: no sync needed)
    for (int i = 0; i < NN; i++) {
      float acc = 0.f;
      for (int j = 0; j < NN; j++) acc += sA[i*NN+j] * sv[j*128 + c];
      float e = 0.5f * (acc - sv[i*128 + c]);
      size_t o2 = ((size_t)T_*B_ + t) * DD + i*128 + c;
      __nv_bfloat16 h = __float2bfloat16(e);
      g_Shi[o2] = h;
      g_Slo[o2] = __float2bfloat16(e - __bfloat162float(h));
      if (t == T_-1) g_E[i*128 + c] = e;
    }
  }
}

// pre[t, b=0, :] += corr_tail[t, :] - biasV  (bias was added to tail rows too)
__global__ void k_addcorr() {
  int idx = blockIdx.x * 256 + threadIdx.x;
  int t = idx >> 10, n = idx & 1023;
  g_pre[(size_t)t * B_ * GG + n] += g_pre[((size_t)T_*B_ + t) * GG + n] - g_biasV[n];
}

__global__ void k_fixF0(const float* __restrict__ W2) {
  int i = blockIdx.x, cc = threadIdx.x;
  __shared__ float se[128];
  se[cc] = g_E[i*128 + cc];
  __syncthreads();
  float acc = 0.f;
  for (int k = 0; k < 128; k++) acc += se[k] * W2[k*128 + cc];
  g_F[i*128 + cc] += acc;
}

// ============================ mma.sync split-bf16 GEMM (K-folded) ============================
// C = [Ahi|Ahi|Alo][M,3*2176] @ [Bhi|Blo|Bhi]^T : one bf16 GEMM, virtual K = 6528.
#define GSTG 32768

__device__ __forceinline__ void issue2(uint32_t dst, const __nv_bfloat16* A,
                                       const __nv_bfloat16* B, int m0, int n0,
                                       int cc, int tid) {
#pragma unroll
  for (int r = 0; r < 4; r++) {
    int idx = tid + r * 256;
    int row = idx >> 3, q = idx & 7;
    uint32_t off = (uint32_t)(row << 7) + (q << 4);
    off ^= (off >> 3) & 0x70;
    cp16(dst + off,         A + ((size_t)(m0 + row) * DD + cc * 64 + q * 8));
    cp16(dst + 16384 + off, B + ((size_t)(n0 + row) * DD + cc * 64 + q * 8));
  }
}

__global__ void __launch_bounds__(256, 2)
k_mmagemm(const __nv_bfloat16* __restrict__ Ahi, const __nv_bfloat16* __restrict__ Alo,
          const __nv_bfloat16* __restrict__ Bhi, const __nv_bfloat16* __restrict__ Blo,
          float* __restrict__ C, const float* __restrict__ bias) {
  extern __shared__ char sm[];
  uint32_t sb = smem_u32(sm);
  int tid = threadIdx.x, lane = tid & 31, w = tid >> 5;
  int wm = (w & 3) * 32;
  int wn = (w >> 2) * 64;
  int m0 = blockIdx.y << 7, n0 = blockIdx.x << 7;

  float acc[2][8][4];
#pragma unroll
  for (int mt = 0; mt < 2; mt++)
#pragma unroll
    for (int nt = 0; nt < 8; nt++)
#pragma unroll
      for (int j = 0; j < 4; j++) acc[mt][nt][j] = 0.f;

  const int NCH = 102;    // 3 * 34
  issue2(sb + 0*GSTG, Ahi, Bhi, m0, n0, 0, tid);
  asm volatile("cp.async.commit_group;");
  issue2(sb + 1*GSTG, Ahi, Bhi, m0, n0, 1, tid);
  asm volatile("cp.async.commit_group;");
  issue2(sb + 2*GSTG, Ahi, Bhi, m0, n0, 2, tid);
  asm volatile("cp.async.commit_group;");

  int stg = 0;
#pragma unroll 1
  for (int ch = 0; ch < NCH; ch++) {
    if (ch < NCH - 2)       asm volatile("cp.async.wait_group 2;");
    else if (ch == NCH - 2) asm volatile("cp.async.wait_group 1;");
    else                    asm volatile("cp.async.wait_group 0;");
    __syncthreads();
    uint32_t cur = sb + (uint32_t)stg * GSTG;

#pragma unroll
    for (int ks = 0; ks < 4; ks++) {
      uint32_t ah[2][4];
#pragma unroll
      for (int mt = 0; mt < 2; mt++) {
        uint32_t row = wm + mt * 16 + (lane & 15);
        uint32_t off = (row << 7) + ks * 32 + ((lane >> 4) << 4);
        off ^= (off >> 3) & 0x70;
        ldsm4(cur + off, ah[mt][0], ah[mt][1], ah[mt][2], ah[mt][3]);
      }
      uint32_t bh[4][4];
#pragma unroll
      for (int ng = 0; ng < 4; ng++) {
        uint32_t row = wn + ng * 16 + (lane & 15);
        uint32_t off = (row << 7) + ks * 32 + ((lane >> 4) << 4);
        off ^= (off >> 3) & 0x70;
        ldsm4(cur + 16384 + off, bh[ng][0], bh[ng][1], bh[ng][2], bh[ng][3]);
      }
#pragma unroll
      for (int mt = 0; mt < 2; mt++)
#pragma unroll
        for (int ng = 0; ng < 4; ng++) {
          mma16816(acc[mt][ng*2],   ah[mt], bh[ng][0], bh[ng][2]);
          mma16816(acc[mt][ng*2+1], ah[mt], bh[ng][1], bh[ng][3]);
        }
    }
    __syncthreads();
    int nx = ch + 3;
    if (nx < NCH) {
      int s = (nx >= 68) ? 2 : ((nx >= 34) ? 1 : 0);
      const __nv_bfloat16* As_ = (s == 2) ? Alo : Ahi;
      const __nv_bfloat16* Bs_ = (s == 1) ? Blo : Bhi;
      issue2(cur, As_, Bs_, m0, n0, nx - s * 34, tid);
      asm volatile("cp.async.commit_group;");
    }
    stg = (stg + 1 == 3) ? 0 : stg + 1;
  }

#pragma unroll
  for (int mt = 0; mt < 2; mt++) {
    int r = m0 + wm + mt * 16 + (lane >> 2);
#pragma unroll
    for (int nt = 0; nt < 8; nt++) {
      int cc = n0 + wn + nt * 8 + (lane & 3) * 2;
      float b0 = 0.f, b1 = 0.f;
      if (bias) { b0 = bias[cc]; b1 = bias[cc + 1]; }
      float2 v0 = make_float2(acc[mt][nt][0] + b0, acc[mt][nt][1] + b1);
      float2 v1 = make_float2(acc[mt][nt][2] + b0, acc[mt][nt][3] + b1);
      *(float2*)(C + (size_t)r * GG + cc) = v0;
      *(float2*)(C + (size_t)(r + 8) * GG + cc) = v1;
    }
  }
}

// ============================ persistent fused forward LSTM ============================
#define L_OBHI 0
#define L_OBLO 16384
#define L_OAHI 32768
#define L_OALO 98304
#define L_SMEM 163840

__device__ __forceinline__ float sigf(float x) { return 1.f / (1.f + expf(-x)); }

__global__ void __launch_bounds__(256, 1)
k_lstm_persist(const float* __restrict__ pre, const float* __restrict__ Whh,
               float* __restrict__ hfin) {
  extern __shared__ char sm[];
  uint32_t sb = smem_u32(sm);
  int tid = threadIdx.x, lane = tid & 31, w = tid >> 5;
  int jb = blockIdx.x;

  for (int idx = tid; idx < 32 * 32; idx += 256) {
    int row = idx >> 5, q32 = idx & 31;
    int kc = q32 >> 3, q = q32 & 7;
    int g = row >> 3, jj = row & 7;
    const float* src = Whh + (size_t)(g * 256 + jb * 8 + jj) * LH_ + q32 * 8;
    float vv[8];
    *(float4*)&vv[0] = *(const float4*)src;
    *(float4*)&vv[4] = *(const float4*)(src + 4);
    __nv_bfloat16 h8[8], l8[8];
#pragma unroll
    for (int e = 0; e < 8; e++) {
      h8[e] = __float2bfloat16(vv[e]);
      l8[e] = __float2bfloat16(vv[e] - __bfloat162float(h8[e]));
    }
    uint32_t off = (uint32_t)(row << 7) + (q << 4);
    off ^= (off >> 3) & 0x70;
    *(float4*)(sm + L_OBHI + kc * 4096 + off) = *(float4*)h8;
    *(float4*)(sm + L_OBLO + kc * 4096 + off) = *(float4*)l8;
  }
  float c4[4] = {0.f, 0.f, 0.f, 0.f};
  __syncthreads();

  int r0 = w * 16 + (lane >> 2);
  int j  = jb * 8 + (lane & 3) * 2;

#pragma unroll 1
  for (int t = 0; t < T_; t++) {
    const float* pb = pre + (size_t)t * B_ * GG;
    float prv[4][4];
#pragma unroll
    for (int e = 0; e < 4; e++) {
      int b = r0 + (e >> 1) * 8;
      int jc = j + (e & 1);
      const float* pr = pb + (size_t)b * GG + jc;
      prv[0][e] = pr[0];
      prv[1][e] = pr[256];
      prv[2][e] = pr[512];
      prv[3][e] = pr[768];
    }

    if (t > 0) {
      if (tid == 0) {
        volatile unsigned* p = &g_barcnt;
        while (*p < (unsigned)(LCTA * t)) { }
      }
      __syncthreads();
      __threadfence();
    }
    const __nv_bfloat16* Hh = g_hhi[t & 1];
    const __nv_bfloat16* Hl = g_hlo[t & 1];
#pragma unroll
    for (int r = 0; r < 16; r++) {
      int idx = tid + r * 256;
      int row = idx >> 5, q32 = idx & 31;
      int kc = q32 >> 3, q = q32 & 7;
      uint32_t off = (uint32_t)(row << 7) + (q << 4);
      off ^= (off >> 3) & 0x70;
      cp16(sb + L_OAHI + kc * 16384 + off, Hh + row * LH_ + q32 * 8);
      cp16(sb + L_OALO + kc * 16384 + off, Hl + row * LH_ + q32 * 8);
    }
    asm volatile("cp.async.commit_group;");
    asm volatile("cp.async.wait_group 0;");
    __syncthreads();

    float acc[4][4];
#pragma unroll
    for (int g = 0; g < 4; g++)
#pragma unroll
      for (int e = 0; e < 4; e++) acc[g][e] = 0.f;

#pragma unroll 1
    for (int kc = 0; kc < 4; kc++) {
      uint32_t abase  = sb + L_OAHI + kc * 16384;
      uint32_t abase2 = sb + L_OALO + kc * 16384;
      uint32_t bbase  = sb + L_OBHI + kc * 4096;
      uint32_t bbase2 = sb + L_OBLO + kc * 4096;
#pragma unroll
      for (int ks = 0; ks < 4; ks++) {
        uint32_t ah[4], al[4];
        {
          uint32_t row = w * 16 + (lane & 15);
          uint32_t off = (row << 7) + ks * 32 + ((lane >> 4) << 4);
          off ^= (off >> 3) & 0x70;
          ldsm4(abase + off, ah[0], ah[1], ah[2], ah[3]);
          ldsm4(abase2 + off, al[0], al[1], al[2], al[3]);
        }
        uint32_t bh[2][4], bl[2][4];
#pragma unroll
        for (int ng = 0; ng < 2; ng++) {
          uint32_t row = ng * 16 + (lane & 15);
          uint32_t off = (row << 7) + ks * 32 + ((lane >> 4) << 4);
          off ^= (off >> 3) & 0x70;
          ldsm4(bbase + off, bh[ng][0], bh[ng][1], bh[ng][2], bh[ng][3]);
          ldsm4(bbase2 + off, bl[ng][0], bl[ng][1], bl[ng][2], bl[ng][3]);
        }
#pragma unroll
        for (int ng = 0; ng < 2; ng++) {
          mma16816(acc[ng*2],   ah, bh[ng][0], bh[ng][2]);
          mma16816(acc[ng*2+1], ah, bh[ng][1], bh[ng][3]);
          mma16816(acc[ng*2],   ah, bl[ng][0], bl[ng][2]);
          mma16816(acc[ng*2+1], ah, bl[ng][1], bl[ng][3]);
          mma16816(acc[ng*2],   al, bh[ng][0], bh[ng][2]);
          mma16816(acc[ng*2+1], al, bh[ng][1], bh[ng][3]);
        }
      }
    }

    __nv_bfloat16* Whi = g_hhi[(t + 1) & 1];
    __nv_bfloat16* Wlo = g_hlo[(t + 1) & 1];
#pragma unroll
    for (int e = 0; e < 4; e++) {
      int b = r0 + (e >> 1) * 8;
      int jc = j + (e & 1);
      float zi = acc[0][e] + prv[0][e];
      float zf = acc[1][e] + prv[1][e];
      float zg = acc[2][e] + prv[2][e];
      float zo = acc[3][e] + prv[3][e];
      float cn = sigf(zf) * c4[e] + sigf(zi) * tanhf(zg);
      c4[e] = cn;
      float hv = sigf(zo) * tanhf(cn);
      __nv_bfloat16 hh = __float2bfloat16(hv);
      Whi[b * LH_ + jc] = hh;
      Wlo[b * LH_ + jc] = __float2bfloat16(hv - __bfloat162float(hh));
      if (t == T_ - 1) hfin[b * LH_ + jc] = hv;
    }
    __threadfence();
    __syncthreads();
    if (tid == 0) atomicAdd(&g_barcnt, 1u);
  }
}

// ============================ tail kernels ============================
__global__ void k_backstep(const float* __restrict__ bih, const float* __restrict__ bhh) {
  int b = blockIdx.x, jx = threadIdx.x;
  const float* pr = g_preb + (size_t)b * GG;
  float zi = pr[jx]       + bih[jx]       + bhh[jx];
  float zg = pr[512 + jx] + bih[512 + jx] + bhh[512 + jx];
  float zo = pr[768 + jx] + bih[768 + jx] + bhh[768 + jx];
  float cn = sigf(zi) * tanhf(zg);
  g_hbk[b * LH_ + jx] = sigf(zo) * tanhf(cn);
}

__global__ void k_pool(const float* __restrict__ hf, float* outp) {
  int idx = blockIdx.x * 256 + threadIdx.x;
  int b = idx >> 9, d = idx & 511;
  float v = (d < 256) ? hf[b * 256 + d] : g_hbk[b * 256 + d - 256];
  v = fmaxf(v, 0.f);
  g_pool[idx] = v;
  if (outp) outp[idx] = v;
}

__global__ void k_cls(const float* __restrict__ Wc, const float* __restrict__ bc,
                      float* __restrict__ outc) {
  int b = blockIdx.x;
  int m = blockIdx.y * 128 + threadIdx.x;
  __shared__ float sp[512];
  int t = threadIdx.x;
  sp[t] = g_pool[b*512 + t]; sp[t+128] = g_pool[b*512 + t + 128];
  sp[t+256] = g_pool[b*512 + t + 256]; sp[t+384] = g_pool[b*512 + t + 384];
  __syncthreads();
  if (m < NC_) {
    float acc = bc[m];
    const float* wr = Wc + (size_t)m * 512;
    for (int d = 0; d < 512; d++) acc += sp[d] * wr[d];
    outc[(size_t)b * NC_ + m] = acc;
  }
}

// ============================ host ============================
extern "C" void kernel_launch(void* const* d_in, const int* in_sizes, int n_in,
                              void* d_out, int out_size) {
  const float* pose1 = (const float*)d_in[0];
  const float* pose2 = (const float*)d_in[1];
  const float* W1    = (const float*)d_in[2];
  const float* b1    = (const float*)d_in[3];
  const float* W2    = (const float*)d_in[4];
  const float* b2    = (const float*)d_in[5];
  const float* Wih_f = (const float*)d_in[6];
  const float* Whh_f = (const float*)d_in[7];
  const float* bih_f = (const float*)d_in[8];
  const float* bhh_f = (const float*)d_in[9];
  const float* Wih_b = (const float*)d_in[10];
  const float* Whh_b = (const float*)d_in[11];
  const float* bih_b = (const float*)d_in[12];
  const float* bhh_b = (const float*)d_in[13];
  const float* Wc    = (const float*)d_in[14];
  const float* bc    = (const float*)d_in[15];
  (void)Whh_b; (void)in_sizes; (void)n_in;
  float* out = (float*)d_out;

  void *pPre, *pF, *pPreb, *pBias, *pHA;
  void *pShi, *pSlo, *pVtHi, *pVtLo, *pWbHi, *pWbLo, *pFhi, *pFlo, *pSlast;
  void *pBar, *pHhi, *pHlo;
  cudaGetSymbolAddress(&pPre,   g_pre);
  cudaGetSymbolAddress(&pF,     g_F);
  cudaGetSymbolAddress(&pPreb,  g_preb);
  cudaGetSymbolAddress(&pBias,  g_biasV);
  cudaGetSymbolAddress(&pHA,    g_hA);
  cudaGetSymbolAddress(&pShi,   g_Shi);
  cudaGetSymbolAddress(&pSlo,   g_Slo);
  cudaGetSymbolAddress(&pVtHi,  g_VtHi);
  cudaGetSymbolAddress(&pVtLo,  g_VtLo);
  cudaGetSymbolAddress(&pWbHi,  g_WbHi);
  cudaGetSymbolAddress(&pWbLo,  g_WbLo);
  cudaGetSymbolAddress(&pFhi,   g_Fhi);
  cudaGetSymbolAddress(&pFlo,   g_Flo);
  cudaGetSymbolAddress(&pSlast, g_Slast);
  cudaGetSymbolAddress(&pBar,   g_barcnt);
  cudaGetSymbolAddress(&pHhi,   g_hhi);
  cudaGetSymbolAddress(&pHlo,   g_hlo);

  float* pool_dst = nullptr;
  float* cls_dst  = nullptr;
  if (out_size == B_*512 + B_*NC_)      { pool_dst = out; cls_dst = out + B_*512; }
  else if (out_size == B_*NC_)          { cls_dst = out; }
  else if (out_size == B_*512)          { pool_dst = out; }
  else { pool_dst = out; if (out_size >= B_*512 + B_*NC_) cls_dst = out + B_*512; }

  cudaFuncSetAttribute(k_mmagemm, cudaFuncAttributeMaxDynamicSharedMemorySize, 3*GSTG);
  cudaFuncSetAttribute(k_lstm_persist, cudaFuncAttributeMaxDynamicSharedMemorySize, L_SMEM);

  // (0) Vt = fold(W2, Wih_f), split bf16 directly
  k_vfold<<<dim3(1, 8, 17), 256>>>(Wih_f, W2, (__nv_bfloat16*)pVtHi, (__nv_bfloat16*)pVtLo);
  // (1) biasV
  k_biasV<<<GG, 256>>>(Wih_f, bih_f, bhh_f, b2);
  // (2) GCN layer 1 -> S split (+E tail rows, Slast, E[T-1])
  k_layer1<<<T_*B_, 128>>>(pose1, pose2, W1, b1);
  // (3) pre(+corr tail) = [S;E] @ V + biasV    <-- ncu-profiled slot
  k_mmagemm<<<dim3(8, MR/128), 256, 3*GSTG>>>((const __nv_bfloat16*)pShi, (const __nv_bfloat16*)pSlo,
                                              (const __nv_bfloat16*)pVtHi, (const __nv_bfloat16*)pVtLo,
                                              (float*)pPre, (const float*)pBias);
  // (4) pre[t, b=0] += corr - biasV
  k_addcorr<<<(T_*GG)/256, 256>>>();
  // (5..7) backward features: F = Slast @ W2 + b2; fix b=0; split F
  k_sgemm<<<dim3(1, (B_*NN)/128, 1), 256>>>(B_*NN, 128, 128, (const float*)pSlast, W2,
                                            (float*)pF, b2, 0LL, 0LL, 0LL);
  k_fixF0<<<NN, 128>>>(W2);
  k_split<<<(B_*DD/4 + 255)/256, 256>>>((const float*)pF, (__nv_bfloat16*)pFhi, (__nv_bfloat16*)pFlo, B_*DD/4);
  // (8) split Wih_b
  k_split<<<(GG*DD/4 + 255)/256, 256>>>(Wih_b, (__nv_bfloat16*)pWbHi, (__nv_bfloat16*)pWbLo, GG*DD/4);
  // (9) pre_b = F @ Wih_b^T
  k_mmagemm<<<dim3(8, 1), 256, 3*GSTG>>>((const __nv_bfloat16*)pFhi, (const __nv_bfloat16*)pFlo,
                                         (const __nv_bfloat16*)pWbHi, (const __nv_bfloat16*)pWbLo,
                                         (float*)pPreb, nullptr);

  // persistent forward LSTM
  cudaMemsetAsync(pBar, 0, sizeof(unsigned));
  cudaMemsetAsync(pHhi, 0, (size_t)B_ * LH_ * sizeof(__nv_bfloat16));
  cudaMemsetAsync(pHlo, 0, (size_t)B_ * LH_ * sizeof(__nv_bfloat16));
  k_lstm_persist<<<LCTA, 256, L_SMEM>>>((const float*)pPre, Whh_f, (float*)pHA);

  k_backstep<<<B_, 256>>>(bih_b, bhh_b);
  k_pool<<<(B_*512)/256, 256>>>((const float*)pHA, pool_dst);
  if (cls_dst) k_cls<<<dim3(B_, 5), 128>>>(Wc, bc, cls_dst);
}